// round 12
// baseline (speedup 1.0000x reference)
#include <cuda_runtime.h>
#include <cuda_fp16.h>
#include <cstdint>

// ---------------- problem constants ----------------
#define SEQ   2048
#define HID   1024
#define H3    3072
#define NHEAD 16
#define HD    64
#define WIN   128
#define GSTRIDE 64

// ---------------- mma / ldmatrix / cp.async helpers ----------------
__device__ __forceinline__ void mma16816h(float& c0, float& c1, float& c2, float& c3,
                                          uint32_t a0, uint32_t a1, uint32_t a2, uint32_t a3,
                                          uint32_t b0, uint32_t b1) {
    asm volatile(
        "mma.sync.aligned.m16n8k16.row.col.f32.f16.f16.f32 "
        "{%0,%1,%2,%3}, {%4,%5,%6,%7}, {%8,%9}, {%0,%1,%2,%3};"
        : "+f"(c0), "+f"(c1), "+f"(c2), "+f"(c3)
        : "r"(a0), "r"(a1), "r"(a2), "r"(a3), "r"(b0), "r"(b1));
}
__device__ __forceinline__ void ldm_x4(uint32_t& r0, uint32_t& r1, uint32_t& r2, uint32_t& r3,
                                       uint32_t addr) {
    asm volatile("ldmatrix.sync.aligned.m8n8.x4.shared.b16 {%0,%1,%2,%3}, [%4];"
                 : "=r"(r0), "=r"(r1), "=r"(r2), "=r"(r3) : "r"(addr));
}
__device__ __forceinline__ uint32_t smem_u32(const void* p) {
    uint32_t a;
    asm("{ .reg .u64 t; cvta.to.shared.u64 t, %1; cvt.u32.u64 %0, t; }" : "=r"(a) : "l"(p));
    return a;
}
__device__ __forceinline__ void cp16(uint32_t saddr, const void* gptr) {
    asm volatile("cp.async.cg.shared.global [%0], [%1], 16;" :: "r"(saddr), "l"(gptr));
}
#define CP_COMMIT() asm volatile("cp.async.commit_group;" ::: "memory")
#define CP_WAIT1()  asm volatile("cp.async.wait_group 1;" ::: "memory")
#define CP_WAIT0()  asm volatile("cp.async.wait_group 0;" ::: "memory")

// fp16 helpers
__device__ __forceinline__ uint32_t packh2(float a, float b) {
    __half2 h = __floats2half2_rn(a, b);
    uint32_t r; *(__half2*)&r = h; return r;
}
__device__ __forceinline__ void hsplit(float x, __half& hi, __half& lo) {
    hi = __float2half_rn(x);
    lo = __float2half_rn(x - __half2float(hi));
}
__device__ __forceinline__ void hsplit2(float a, float b, uint32_t& hi, uint32_t& lo) {
    __half ha = __float2half_rn(a), hb = __float2half_rn(b);
    float ra = a - __half2float(ha), rb = b - __half2float(hb);
    *(__half2*)&hi = __halves2half2(ha, hb);
    lo = packh2(ra, rb);
}

// ---------------- scratch (device globals) ----------------
__device__ float g_qkv[SEQ * H3];
__device__ __align__(16) __half g_xh[SEQ * HID];
__device__ __align__(16) __half g_wqh[H3 * HID], g_wql[H3 * HID];
__device__ __align__(16) __half g_woh[HID * HID], g_wol[HID * HID];
__device__ __align__(16) __half g_ah[SEQ * HID];
__device__ __align__(16) __half g_qh[NHEAD * SEQ * 64];
__device__ __align__(16) __half g_kh[NHEAD * SEQ * 64], g_kl[NHEAD * SEQ * 64];
__device__ __align__(16) __half g_vth[NHEAD * 64 * SEQ], g_vtl[NHEAD * 64 * SEQ];
__device__ __align__(16) __half g_kgh[NHEAD * 32 * 64], g_kgl[NHEAD * 32 * 64];
__device__ __align__(16) __half g_vtgh[NHEAD * 64 * 32], g_vtgl[NHEAD * 64 * 32];

// ---------------- conversions ----------------
__global__ __launch_bounds__(256) void conv_half(const float* __restrict__ in,
                                                 __half* __restrict__ out, int n4) {
    int i = blockIdx.x * blockDim.x + threadIdx.x;
    if (i >= n4) return;
    float4 v = ((const float4*)in)[i];
    uint32_t* op = (uint32_t*)out;
    op[2 * i]     = packh2(v.x, v.y);
    op[2 * i + 1] = packh2(v.z, v.w);
}
__global__ __launch_bounds__(256) void split_half(const float* __restrict__ in,
                                                  __half* __restrict__ hi,
                                                  __half* __restrict__ lo, int n4) {
    int i = blockIdx.x * blockDim.x + threadIdx.x;
    if (i >= n4) return;
    float4 v = ((const float4*)in)[i];
    uint32_t h0, l0, h1, l1;
    hsplit2(v.x, v.y, h0, l0);
    hsplit2(v.z, v.w, h1, l1);
    uint32_t* hp = (uint32_t*)hi;
    uint32_t* lp = (uint32_t*)lo;
    hp[2 * i] = h0; hp[2 * i + 1] = h1;
    lp[2 * i] = l0; lp[2 * i + 1] = l1;
}

// ---------------- fp16 2-term GEMM: C = A @ (Bh+Bl)^T ----------------
// Templated on BM (128 or 64). 256 thr, 8 warps 2(M)x4(N).
// BM=128: warp tile 64x32; BM=64: warp tile 32x32 (doubles grid for small GEMMs).
#define SSTR 40
#define BUFE (128 * SSTR)

template<int BM>
__global__ __launch_bounds__(256) void gemm_f16(const __half* __restrict__ Ag,
                                                const __half* __restrict__ Bhg,
                                                const __half* __restrict__ Blg,
                                                float* __restrict__ C,
                                                int M, int N, int K) {
    constexpr int IM = BM / 32;            // 4 or 2
    constexpr int ABUF = BM * SSTR;        // A elems per stage
    constexpr int STGE = ABUF + 2 * BUFE;  // elems per stage

    extern __shared__ __half smf[];
    const uint32_t sbase = smem_u32(smf);

    const int tid = threadIdx.x;
    const int wid = tid >> 5;
    const int lane = tid & 31;
    const int g = lane >> 2;
    const int t = lane & 3;
    const int warp_m = (wid & 1) * (BM / 2);
    const int warp_n = (wid >> 1) * 32;
    const int tile_m = blockIdx.y * BM;
    const int tile_n = blockIdx.x * 128;

    const int a_row = warp_m + ((lane >> 3) & 1) * 8 + (lane & 7);
    const int a_col = (lane >> 4) * 8;
    const int b_row = warp_n + (lane >> 4) * 8 + (lane & 7);
    const int b_col = ((lane >> 3) & 1) * 8;

    float acc[IM][4][4];
#pragma unroll
    for (int im = 0; im < IM; im++)
#pragma unroll
        for (int jn = 0; jn < 4; jn++)
#pragma unroll
            for (int c = 0; c < 4; c++) acc[im][jn][c] = 0.f;

    auto load_stage = [&](int st, int k0) {
        const uint32_t sb = sbase + (uint32_t)st * STGE * 2;
        for (int idx = tid; idx < BM * 4; idx += 256) {
            const int row = idx >> 2;
            const int c8  = (idx & 3) * 8;
            cp16(sb + (uint32_t)(row * SSTR + c8) * 2,
                 Ag + (size_t)(tile_m + row) * K + k0 + c8);
        }
        for (int idx = tid; idx < 512; idx += 256) {
            const int row = idx >> 2;
            const int c8  = (idx & 3) * 8;
            const uint32_t so = (uint32_t)(row * SSTR + c8) * 2;
            const size_t goB = (size_t)(tile_n + row) * K + k0 + c8;
            cp16(sb + ABUF * 2 + so,              Bhg + goB);
            cp16(sb + (ABUF + BUFE) * 2 + so,     Blg + goB);
        }
    };

    const int nchunks = K >> 5;
    load_stage(0, 0);
    CP_COMMIT();

    for (int ch = 0; ch < nchunks; ch++) {
        if (ch + 1 < nchunks) load_stage((ch + 1) & 1, (ch + 1) << 5);
        CP_COMMIT();
        CP_WAIT1();
        __syncthreads();

        const uint32_t sb = sbase + (uint32_t)(ch & 1) * STGE * 2;
#pragma unroll
        for (int ks = 0; ks < 32; ks += 16) {
            uint32_t aH[IM][4];
#pragma unroll
            for (int im = 0; im < IM; im++) {
                const uint32_t ad = sb + (uint32_t)((a_row + im * 16) * SSTR + ks + a_col) * 2;
                ldm_x4(aH[im][0], aH[im][1], aH[im][2], aH[im][3], ad);
            }
#pragma unroll
            for (int jp = 0; jp < 2; jp++) {
                uint32_t bh0, bh1, bh2, bh3, bl0, bl1, bl2, bl3;
                const uint32_t bd = sb + ABUF * 2
                                  + (uint32_t)((b_row + jp * 16) * SSTR + ks + b_col) * 2;
                ldm_x4(bh0, bh1, bh2, bh3, bd);
                ldm_x4(bl0, bl1, bl2, bl3, bd + BUFE * 2);
                // hi-term pass over all accumulators, then lo-term pass:
                // max RAW distance between writes to the same accumulator.
#pragma unroll
                for (int im = 0; im < IM; im++) {
                    float* a0p = acc[im][2 * jp];
                    float* a1p = acc[im][2 * jp + 1];
                    mma16816h(a0p[0], a0p[1], a0p[2], a0p[3],
                              aH[im][0], aH[im][1], aH[im][2], aH[im][3], bh0, bh1);
                    mma16816h(a1p[0], a1p[1], a1p[2], a1p[3],
                              aH[im][0], aH[im][1], aH[im][2], aH[im][3], bh2, bh3);
                }
#pragma unroll
                for (int im = 0; im < IM; im++) {
                    float* a0p = acc[im][2 * jp];
                    float* a1p = acc[im][2 * jp + 1];
                    mma16816h(a0p[0], a0p[1], a0p[2], a0p[3],
                              aH[im][0], aH[im][1], aH[im][2], aH[im][3], bl0, bl1);
                    mma16816h(a1p[0], a1p[1], a1p[2], a1p[3],
                              aH[im][0], aH[im][1], aH[im][2], aH[im][3], bl2, bl3);
                }
            }
        }
        __syncthreads();
    }

#pragma unroll
    for (int im = 0; im < IM; im++) {
        const int row = tile_m + warp_m + im * 16 + g;
#pragma unroll
        for (int jn = 0; jn < 4; jn++) {
            const int col = tile_n + warp_n + jn * 8 + 2 * t;
            float2 v0; v0.x = acc[im][jn][0]; v0.y = acc[im][jn][1];
            float2 v1; v1.x = acc[im][jn][2]; v1.y = acc[im][jn][3];
            *(float2*)(C + (size_t)row * N + col)       = v0;
            *(float2*)(C + (size_t)(row + 8) * N + col) = v1;
        }
    }
}

#define GF_SMEM128 (2 * (128 * SSTR + 2 * BUFE) * 2)
#define GF_SMEM64  (2 * (64 * SSTR + 2 * BUFE) * 2)

// ---------------- prep: per-head fp16 Q (plain) / K,Vt (hi+lo) ----------------
#define PVS 66
__global__ __launch_bounds__(256) void prep_attn() {
    const int st = blockIdx.x;
    const int h  = blockIdx.y;
    const int s0 = st * 64;
    const int tid = threadIdx.x;

    __shared__ __half vth[64][PVS], vtl[64][PVS];

    for (int idx = tid; idx < 1024; idx += 256) {
        const int r = idx >> 4, c4 = (idx & 15) << 2;
        const size_t base = (size_t)(s0 + r) * H3 + h * HD + c4;
        const size_t qo = (size_t)h * SEQ * 64 + (size_t)(s0 + r) * 64 + c4;
        float4 q = *(const float4*)(g_qkv + base);
        *(uint32_t*)&g_qh[qo]     = packh2(q.x * 0.125f, q.y * 0.125f);
        *(uint32_t*)&g_qh[qo + 2] = packh2(q.z * 0.125f, q.w * 0.125f);
        float4 k = *(const float4*)(g_qkv + base + HID);
        uint32_t h0, l0, h1, l1;
        hsplit2(k.x, k.y, h0, l0);
        hsplit2(k.z, k.w, h1, l1);
        *(uint32_t*)&g_kh[qo] = h0; *(uint32_t*)&g_kh[qo + 2] = h1;
        *(uint32_t*)&g_kl[qo] = l0; *(uint32_t*)&g_kl[qo + 2] = l1;
        float4 v = *(const float4*)(g_qkv + base + 2 * HID);
        hsplit(v.x, vth[c4 + 0][r], vtl[c4 + 0][r]);
        hsplit(v.y, vth[c4 + 1][r], vtl[c4 + 1][r]);
        hsplit(v.z, vth[c4 + 2][r], vtl[c4 + 2][r]);
        hsplit(v.w, vth[c4 + 3][r], vtl[c4 + 3][r]);
    }
    __syncthreads();

    for (int idx = tid; idx < 2048; idx += 256) {
        const int d = idx >> 5, cp = (idx & 31) << 1;
        const size_t vo = (size_t)h * 64 * SEQ + (size_t)d * SEQ + s0 + cp;
        *(uint32_t*)&g_vth[vo] = *(const uint32_t*)&vth[d][cp];
        *(uint32_t*)&g_vtl[vo] = *(const uint32_t*)&vtl[d][cp];
    }
    if (tid < 16) {
        const int c4 = tid * 4;
        float4 k = *(const float4*)(g_qkv + (size_t)s0 * H3 + HID + h * HD + c4);
        uint32_t h0, l0, h1, l1;
        hsplit2(k.x, k.y, h0, l0);
        hsplit2(k.z, k.w, h1, l1);
        const size_t ko = (size_t)h * 32 * 64 + (size_t)st * 64 + c4;
        *(uint32_t*)&g_kgh[ko] = h0; *(uint32_t*)&g_kgh[ko + 2] = h1;
        *(uint32_t*)&g_kgl[ko] = l0; *(uint32_t*)&g_kgl[ko + 2] = l1;
    }
    if (tid < 64) {
        const size_t go = (size_t)h * 64 * 32 + (size_t)tid * 32 + st;
        g_vtgh[go] = vth[tid][0];
        g_vtgl[go] = vtl[tid][0];
    }
}

// ================= MMA attention core (fp16 2-term, ILP-ordered) =================
#define MASKV (-3.0e38f)
#define ATS   72
#define ATILE (64 * ATS)
#define AT_SMEM ((1 + 8) * ATILE * 2)

template<int NKT, int MODE>
__device__ __forceinline__ void attn_compute(
    uint32_t sKh, uint32_t sVh, int kb, int qr0,
    int t, int brow, int bcol,
    const uint32_t qh[4][4],
    float o[8][4], float& m0, float& m1, float& l0, float& l1)
{
    constexpr int NJ = NKT / 8;
    float sc[NJ][4];

    // ---- S = Q (Kh + Kl)^T ----
#pragma unroll
    for (int jp = 0; jp < NKT / 16; jp++) {
#pragma unroll
        for (int e = 0; e < 4; e++) { sc[2 * jp][e] = 0.f; sc[2 * jp + 1][e] = 0.f; }
#pragma unroll
        for (int c = 0; c < 4; c++) {
            uint32_t b0, b1, b2, b3, d0, d1, d2, d3;
            const uint32_t ka = sKh + (uint32_t)((jp * 16 + brow) * ATS + c * 16 + bcol) * 2;
            ldm_x4(b0, b1, b2, b3, ka);
            ldm_x4(d0, d1, d2, d3, ka + ATILE * 2);
            float* s0p = sc[2 * jp];
            float* s1p = sc[2 * jp + 1];
            // alternate accumulators to break RAW chains
            mma16816h(s0p[0], s0p[1], s0p[2], s0p[3],
                      qh[c][0], qh[c][1], qh[c][2], qh[c][3], b0, b1);
            mma16816h(s1p[0], s1p[1], s1p[2], s1p[3],
                      qh[c][0], qh[c][1], qh[c][2], qh[c][3], b2, b3);
            mma16816h(s0p[0], s0p[1], s0p[2], s0p[3],
                      qh[c][0], qh[c][1], qh[c][2], qh[c][3], d0, d1);
            mma16816h(s1p[0], s1p[1], s1p[2], s1p[3],
                      qh[c][0], qh[c][1], qh[c][2], qh[c][3], d2, d3);
        }
    }

    // ---- mask + row max ----
    float tm0 = MASKV, tm1 = MASKV;
#pragma unroll
    for (int jn = 0; jn < NJ; jn++) {
#pragma unroll
        for (int e = 0; e < 2; e++) {
            if (MODE < 2) {
                const int ci  = jn * 8 + 2 * t + e;
                const int key = (MODE == 1) ? (ci * GSTRIDE) : (kb + ci);
                int d0 = qr0 - key; d0 = d0 < 0 ? -d0 : d0;
                int d1 = qr0 + 8 - key; d1 = d1 < 0 ? -d1 : d1;
                const bool in0 = (MODE == 1) ? (d0 > WIN) : (d0 <= WIN);
                const bool in1 = (MODE == 1) ? (d1 > WIN) : (d1 <= WIN);
                if (!in0) sc[jn][e]     = MASKV;
                if (!in1) sc[jn][2 + e] = MASKV;
            }
            tm0 = fmaxf(tm0, sc[jn][e]);
            tm1 = fmaxf(tm1, sc[jn][2 + e]);
        }
    }
    tm0 = fmaxf(tm0, __shfl_xor_sync(0xffffffffu, tm0, 1));
    tm0 = fmaxf(tm0, __shfl_xor_sync(0xffffffffu, tm0, 2));
    tm1 = fmaxf(tm1, __shfl_xor_sync(0xffffffffu, tm1, 1));
    tm1 = fmaxf(tm1, __shfl_xor_sync(0xffffffffu, tm1, 2));

    const float mn0 = fmaxf(m0, tm0), mn1 = fmaxf(m1, tm1);
    const float e0 = __expf(m0 - mn0), e1 = __expf(m1 - mn1);
    m0 = mn0; m1 = mn1; l0 *= e0; l1 *= e1;
#pragma unroll
    for (int nb = 0; nb < 8; nb++) {
        o[nb][0] *= e0; o[nb][1] *= e0; o[nb][2] *= e1; o[nb][3] *= e1;
    }

    // ---- P = exp(S - m) (plain fp16); O += P (Vh + Vl) ----
    float s0 = 0.f, s1 = 0.f;
#pragma unroll
    for (int c = 0; c < NKT / 16; c++) {
        const float p00 = __expf(sc[2 * c][0] - m0);
        const float p01 = __expf(sc[2 * c][1] - m0);
        const float p02 = __expf(sc[2 * c][2] - m1);
        const float p03 = __expf(sc[2 * c][3] - m1);
        const float p10 = __expf(sc[2 * c + 1][0] - m0);
        const float p11 = __expf(sc[2 * c + 1][1] - m0);
        const float p12 = __expf(sc[2 * c + 1][2] - m1);
        const float p13 = __expf(sc[2 * c + 1][3] - m1);
        s0 += (p00 + p01) + (p10 + p11);
        s1 += (p02 + p03) + (p12 + p13);
        uint32_t ah[4];
        ah[0] = packh2(p00, p01);
        ah[1] = packh2(p02, p03);
        ah[2] = packh2(p10, p11);
        ah[3] = packh2(p12, p13);
#pragma unroll
        for (int np = 0; np < 4; np++) {
            uint32_t v0, v1, v2, v3, w0, w1, w2, w3;
            const uint32_t va = sVh + (uint32_t)((np * 16 + brow) * ATS + c * 16 + bcol) * 2;
            ldm_x4(v0, v1, v2, v3, va);
            ldm_x4(w0, w1, w2, w3, va + ATILE * 2);
            float* oa = o[2 * np];
            float* ob = o[2 * np + 1];
            // alternate oa/ob to break RAW chains
            mma16816h(oa[0], oa[1], oa[2], oa[3], ah[0], ah[1], ah[2], ah[3], v0, v1);
            mma16816h(ob[0], ob[1], ob[2], ob[3], ah[0], ah[1], ah[2], ah[3], v2, v3);
            mma16816h(oa[0], oa[1], oa[2], oa[3], ah[0], ah[1], ah[2], ah[3], w0, w1);
            mma16816h(ob[0], ob[1], ob[2], ob[3], ah[0], ah[1], ah[2], ah[3], w2, w3);
        }
    }
    s0 += __shfl_xor_sync(0xffffffffu, s0, 1);
    s0 += __shfl_xor_sync(0xffffffffu, s0, 2);
    s1 += __shfl_xor_sync(0xffffffffu, s1, 1);
    s1 += __shfl_xor_sync(0xffffffffu, s1, 2);
    l0 += s0; l1 += s1;
}

// ================= band + global-col attention =================
__global__ __launch_bounds__(128) void attn_mma() {
    extern __shared__ __half sm_[];
    const uint32_t sb = smem_u32(sm_);
    const uint32_t sQ = sb;

    const int qt = blockIdx.x, h = blockIdx.y, q0 = qt * 64;
    const int tid = threadIdx.x, wid = tid >> 5, lane = tid & 31;
    const int g = lane >> 2, t = lane & 3;
    const int brow = ((lane >> 4) << 3) + (lane & 7);
    const int bcol = ((lane >> 3) & 1) * 8;

    {
        const __half* qp = g_qh + (size_t)h * SEQ * 64 + (size_t)q0 * 64;
        for (int idx = tid; idx < 512; idx += 128) {
            const int r = idx >> 3, c = idx & 7;
            cp16(sQ + (uint32_t)(r * ATS + c * 8) * 2, qp + r * 64 + c * 8);
        }
    }
    CP_COMMIT();

    const int kb0 = q0 >= WIN ? q0 - WIN : 0;
    const int kb1 = (q0 + 64 + WIN) <= SEQ ? (q0 + 64 + WIN) : SEQ;
    const int nband = (kb1 - kb0) >> 6;
    const int T = nband + 1;

    auto stage_base = [&](int s) { return sb + (uint32_t)(1 + 4 * s) * ATILE * 2; };
    auto stage_band = [&](int s, int kb) {
        const uint32_t b = stage_base(s);
        const __half* khp = g_kh + (size_t)h * SEQ * 64 + (size_t)kb * 64;
        const __half* klp = g_kl + (size_t)h * SEQ * 64 + (size_t)kb * 64;
        const __half* vhp = g_vth + (size_t)h * 64 * SEQ + kb;
        const __half* vlp = g_vtl + (size_t)h * 64 * SEQ + kb;
        for (int idx = tid; idx < 512; idx += 128) {
            const int r = idx >> 3, c = idx & 7;
            const uint32_t so = (uint32_t)(r * ATS + c * 8) * 2;
            cp16(b + so,                 khp + r * 64 + c * 8);
            cp16(b + ATILE * 2 + so,     klp + r * 64 + c * 8);
            cp16(b + 2 * ATILE * 2 + so, vhp + (size_t)r * SEQ + c * 8);
            cp16(b + 3 * ATILE * 2 + so, vlp + (size_t)r * SEQ + c * 8);
        }
    };
    auto stage_glob = [&](int s) {
        const uint32_t b = stage_base(s);
        const __half* khp = g_kgh + (size_t)h * 32 * 64;
        const __half* klp = g_kgl + (size_t)h * 32 * 64;
        const __half* vhp = g_vtgh + (size_t)h * 64 * 32;
        const __half* vlp = g_vtgl + (size_t)h * 64 * 32;
        for (int idx = tid; idx < 256; idx += 128) {
            const int r = idx >> 3, c = idx & 7;
            const uint32_t so = (uint32_t)(r * ATS + c * 8) * 2;
            cp16(b + so,             khp + r * 64 + c * 8);
            cp16(b + ATILE * 2 + so, klp + r * 64 + c * 8);
        }
        for (int idx = tid; idx < 256; idx += 128) {
            const int r = idx >> 2, c = idx & 3;
            const uint32_t so = (uint32_t)(r * ATS + c * 8) * 2;
            cp16(b + 2 * ATILE * 2 + so, vhp + r * 32 + c * 8);
            cp16(b + 3 * ATILE * 2 + so, vlp + r * 32 + c * 8);
        }
    };

    stage_band(0, kb0);
    CP_COMMIT();
    CP_WAIT1();
    __syncthreads();

    uint32_t qh[4][4];
    {
        const int ar = wid * 16 + ((lane >> 3) & 1) * 8 + (lane & 7);
        const int ac = (lane >> 4) * 8;
#pragma unroll
        for (int c = 0; c < 4; c++) {
            const uint32_t ad = sQ + (uint32_t)(ar * ATS + c * 16 + ac) * 2;
            ldm_x4(qh[c][0], qh[c][1], qh[c][2], qh[c][3], ad);
        }
    }

    float o[8][4];
#pragma unroll
    for (int nb = 0; nb < 8; nb++)
#pragma unroll
        for (int c = 0; c < 4; c++) o[nb][c] = 0.f;
    float m0 = -1e30f, m1 = -1e30f, l0 = 0.f, l1 = 0.f;
    const int qr0 = q0 + wid * 16 + g;

    for (int i = 0; i < T; i++) {
        if (i + 1 < T) {
            if (i + 1 < nband) stage_band((i + 1) & 1, kb0 + (i + 1) * 64);
            else stage_glob((i + 1) & 1);
            CP_COMMIT();
            CP_WAIT1();
        } else {
            CP_WAIT0();
        }
        __syncthreads();
        const uint32_t b = stage_base(i & 1);
        if (i < nband)
            attn_compute<64, 0>(b, b + 2 * ATILE * 2, kb0 + i * 64, qr0,
                                t, brow, bcol, qh, o, m0, m1, l0, l1);
        else
            attn_compute<32, 1>(b, b + 2 * ATILE * 2, 0, qr0,
                                t, brow, bcol, qh, o, m0, m1, l0, l1);
        __syncthreads();
    }

    const float i0 = 1.f / l0, i1 = 1.f / l1;
    const int row0 = q0 + wid * 16 + g;
#pragma unroll
    for (int nb = 0; nb < 8; nb++) {
        const size_t ofs0 = (size_t)row0 * HID + h * HD + nb * 8 + 2 * t;
        const size_t ofs1 = ofs0 + (size_t)8 * HID;
        *(uint32_t*)&g_ah[ofs0] = packh2(o[nb][0] * i0, o[nb][1] * i0);
        *(uint32_t*)&g_ah[ofs1] = packh2(o[nb][2] * i1, o[nb][3] * i1);
    }
}

// ================= global rows: MMA over all 2048 keys =================
#define GA_QSZ   (32 * ATS * 2)
#define GA_TILES (2 * 2 * 4 * ATILE * 2)
#define GA_OBUF  (2 * 16 * 64 * 4)
#define GA_SMEM  (GA_QSZ + GA_TILES + GA_OBUF + 256)

__global__ __launch_bounds__(128) void attn_global_mma() {
    extern __shared__ __half smg2[];
    const uint32_t sb = smem_u32(smg2);
    const int h = blockIdx.x;
    const int tid = threadIdx.x, wid = tid >> 5, lane = tid & 31;
    const int g = lane >> 2, t = lane & 3;
    const int rh = wid & 1, kp = wid >> 1;
    const int brow = ((lane >> 4) << 3) + (lane & 7);
    const int bcol = ((lane >> 3) & 1) * 8;

    const uint32_t sQ = sb;
    const uint32_t tiles0 = sb + GA_QSZ;
    float* obuf = (float*)(smg2 + (32 * ATS + 16 * ATILE));
    float* slm  = obuf + 2 * 16 * 64;
    float* sll  = slm + 32;

    {
        const __half* qp = g_qh + (size_t)h * SEQ * 64;
        for (int idx = tid; idx < 256; idx += 128) {
            const int r = idx >> 3, c = idx & 7;
            cp16(sQ + (uint32_t)(r * ATS + c * 8) * 2, qp + (size_t)r * 64 * 64 + c * 8);
        }
    }
    CP_COMMIT();

    auto stage_tiles = [&](int st, int it) {
#pragma unroll
        for (int kpi = 0; kpi < 2; kpi++) {
            const int kt = (it * 2 + kpi) * 64;
            const uint32_t b = tiles0 + (uint32_t)((st * 2 + kpi) * 4) * ATILE * 2;
            const __half* khp = g_kh + (size_t)h * SEQ * 64 + (size_t)kt * 64;
            const __half* klp = g_kl + (size_t)h * SEQ * 64 + (size_t)kt * 64;
            const __half* vhp = g_vth + (size_t)h * 64 * SEQ + kt;
            const __half* vlp = g_vtl + (size_t)h * 64 * SEQ + kt;
            for (int idx = tid; idx < 512; idx += 128) {
                const int r = idx >> 3, c = idx & 7;
                const uint32_t so = (uint32_t)(r * ATS + c * 8) * 2;
                cp16(b + so,                 khp + r * 64 + c * 8);
                cp16(b + ATILE * 2 + so,     klp + r * 64 + c * 8);
                cp16(b + 2 * ATILE * 2 + so, vhp + (size_t)r * SEQ + c * 8);
                cp16(b + 3 * ATILE * 2 + so, vlp + (size_t)r * SEQ + c * 8);
            }
        }
    };

    stage_tiles(0, 0);
    CP_COMMIT();
    CP_WAIT1();
    __syncthreads();

    uint32_t qh[4][4];
    {
        const int ar = rh * 16 + ((lane >> 3) & 1) * 8 + (lane & 7);
        const int ac = (lane >> 4) * 8;
#pragma unroll
        for (int c = 0; c < 4; c++) {
            const uint32_t ad = sQ + (uint32_t)(ar * ATS + c * 16 + ac) * 2;
            ldm_x4(qh[c][0], qh[c][1], qh[c][2], qh[c][3], ad);
        }
    }

    float o[8][4];
#pragma unroll
    for (int nb = 0; nb < 8; nb++)
#pragma unroll
        for (int c = 0; c < 4; c++) o[nb][c] = 0.f;
    float m0 = -1e30f, m1 = -1e30f, l0 = 0.f, l1 = 0.f;

    for (int it = 0; it < 16; it++) {
        if (it + 1 < 16) {
            stage_tiles((it + 1) & 1, it + 1);
            CP_COMMIT();
            CP_WAIT1();
        } else {
            CP_WAIT0();
        }
        __syncthreads();
        const uint32_t b = tiles0 + (uint32_t)(((it & 1) * 2 + kp) * 4) * ATILE * 2;
        attn_compute<64, 2>(b, b + 2 * ATILE * 2, 0, 0,
                            t, brow, bcol, qh, o, m0, m1, l0, l1);
        __syncthreads();
    }

    // ---- merge kp=1 into kp=0 ----
    __syncthreads();
    if (kp == 1) {
        float* ob = obuf + rh * 16 * 64;
#pragma unroll
        for (int nb = 0; nb < 8; nb++) {
            ob[g * 64 + nb * 8 + 2 * t]           = o[nb][0];
            ob[g * 64 + nb * 8 + 2 * t + 1]       = o[nb][1];
            ob[(g + 8) * 64 + nb * 8 + 2 * t]     = o[nb][2];
            ob[(g + 8) * 64 + nb * 8 + 2 * t + 1] = o[nb][3];
        }
        if (t == 0) {
            slm[rh * 16 + g] = m0; slm[rh * 16 + g + 8] = m1;
            sll[rh * 16 + g] = l0; sll[rh * 16 + g + 8] = l1;
        }
    }
    __syncthreads();
    if (kp == 0) {
        const float pm0 = slm[rh * 16 + g], pm1 = slm[rh * 16 + g + 8];
        const float pl0 = sll[rh * 16 + g], pl1 = sll[rh * 16 + g + 8];
        const float M0 = fmaxf(m0, pm0), M1 = fmaxf(m1, pm1);
        const float e0 = __expf(m0 - M0), f0 = __expf(pm0 - M0);
        const float e1 = __expf(m1 - M1), f1 = __expf(pm1 - M1);
        const float L0 = l0 * e0 + pl0 * f0;
        const float L1 = l1 * e1 + pl1 * f1;
        const float i0 = 1.f / L0, i1 = 1.f / L1;
        float* ob = obuf + rh * 16 * 64;
        const int qi0 = (rh * 16 + g) * 64;
        const int qi1 = (rh * 16 + g + 8) * 64;
#pragma unroll
        for (int nb = 0; nb < 8; nb++) {
            const int cc = nb * 8 + 2 * t;
            const float r00 = (o[nb][0] * e0 + ob[g * 64 + cc] * f0) * i0;
            const float r01 = (o[nb][1] * e0 + ob[g * 64 + cc + 1] * f0) * i0;
            const float r10 = (o[nb][2] * e1 + ob[(g + 8) * 64 + cc] * f1) * i1;
            const float r11 = (o[nb][3] * e1 + ob[(g + 8) * 64 + cc + 1] * f1) * i1;
            const size_t ofs0 = (size_t)qi0 * HID + h * HD + cc;
            const size_t ofs1 = (size_t)qi1 * HID + h * HD + cc;
            *(uint32_t*)&g_ah[ofs0] = packh2(r00, r01);
            *(uint32_t*)&g_ah[ofs1] = packh2(r10, r11);
        }
    }
}

// ---------------- launch ----------------
extern "C" void kernel_launch(void* const* d_in, const int* in_sizes, int n_in,
                              void* d_out, int out_size) {
    const float* x    = (const float*)d_in[0];
    const float* Wqkv = (const float*)d_in[1];
    const float* Wout = (const float*)d_in[2];
    float* out = (float*)d_out;

    float* qkv = nullptr;
    cudaGetSymbolAddress((void**)&qkv, g_qkv);
    __half *xh, *wqh, *wql, *woh, *wol, *ah;
    cudaGetSymbolAddress((void**)&xh,  g_xh);
    cudaGetSymbolAddress((void**)&wqh, g_wqh); cudaGetSymbolAddress((void**)&wql, g_wql);
    cudaGetSymbolAddress((void**)&woh, g_woh); cudaGetSymbolAddress((void**)&wol, g_wol);
    cudaGetSymbolAddress((void**)&ah,  g_ah);

    cudaFuncSetAttribute(gemm_f16<128>, cudaFuncAttributeMaxDynamicSharedMemorySize, GF_SMEM128);
    cudaFuncSetAttribute(gemm_f16<64>,  cudaFuncAttributeMaxDynamicSharedMemorySize, GF_SMEM64);
    cudaFuncSetAttribute(attn_mma, cudaFuncAttributeMaxDynamicSharedMemorySize, AT_SMEM);
    cudaFuncSetAttribute(attn_global_mma, cudaFuncAttributeMaxDynamicSharedMemorySize, GA_SMEM);

    // 0) conversions
    conv_half<<<(SEQ * HID / 4 + 255) / 256, 256>>>(x, xh, SEQ * HID / 4);
    split_half<<<(H3 * HID / 4 + 255) / 256, 256>>>(Wqkv, wqh, wql, H3 * HID / 4);
    split_half<<<(HID * HID / 4 + 255) / 256, 256>>>(Wout, woh, wol, HID * HID / 4);

    // 1) qkv = x @ Wqkv^T  (fp16 2-term, 128-row tiles)
    gemm_f16<128><<<dim3(H3 / 128, SEQ / 128), 256, GF_SMEM128>>>(xh, wqh, wql, qkv, SEQ, H3, HID);

    // 2) per-head fp16 operands
    prep_attn<<<dim3(SEQ / 64, NHEAD), 256>>>();

    // 3) sparse attention -> g_ah (fp16)
    attn_mma<<<dim3(SEQ / 64, NHEAD), 128, AT_SMEM>>>();
    attn_global_mma<<<NHEAD, 128, GA_SMEM>>>();

    // 4) out = attn @ Wout^T  (fp16 2-term, 64-row tiles -> 256 CTAs)
    gemm_f16<64><<<dim3(HID / 128, SEQ / 64), 256, GF_SMEM64>>>(ah, woh, wol, out, SEQ, HID, HID);
}

// round 14
// speedup vs baseline: 1.1502x; 1.1502x over previous
#include <cuda_runtime.h>
#include <cuda_fp16.h>
#include <cstdint>

// ---------------- problem constants ----------------
#define SEQ   2048
#define HID   1024
#define H3    3072
#define NHEAD 16
#define HD    64
#define WIN   128
#define GSTRIDE 64

// ---------------- mma / ldmatrix / cp.async helpers ----------------
__device__ __forceinline__ void mma16816h(float& c0, float& c1, float& c2, float& c3,
                                          uint32_t a0, uint32_t a1, uint32_t a2, uint32_t a3,
                                          uint32_t b0, uint32_t b1) {
    asm volatile(
        "mma.sync.aligned.m16n8k16.row.col.f32.f16.f16.f32 "
        "{%0,%1,%2,%3}, {%4,%5,%6,%7}, {%8,%9}, {%0,%1,%2,%3};"
        : "+f"(c0), "+f"(c1), "+f"(c2), "+f"(c3)
        : "r"(a0), "r"(a1), "r"(a2), "r"(a3), "r"(b0), "r"(b1));
}
__device__ __forceinline__ void ldm_x4(uint32_t& r0, uint32_t& r1, uint32_t& r2, uint32_t& r3,
                                       uint32_t addr) {
    asm volatile("ldmatrix.sync.aligned.m8n8.x4.shared.b16 {%0,%1,%2,%3}, [%4];"
                 : "=r"(r0), "=r"(r1), "=r"(r2), "=r"(r3) : "r"(addr));
}
__device__ __forceinline__ uint32_t smem_u32(const void* p) {
    uint32_t a;
    asm("{ .reg .u64 t; cvta.to.shared.u64 t, %1; cvt.u32.u64 %0, t; }" : "=r"(a) : "l"(p));
    return a;
}
__device__ __forceinline__ void cp16(uint32_t saddr, const void* gptr) {
    asm volatile("cp.async.cg.shared.global [%0], [%1], 16;" :: "r"(saddr), "l"(gptr));
}
#define CP_COMMIT() asm volatile("cp.async.commit_group;" ::: "memory")
#define CP_WAIT1()  asm volatile("cp.async.wait_group 1;" ::: "memory")
#define CP_WAIT0()  asm volatile("cp.async.wait_group 0;" ::: "memory")

// fp16 helpers
__device__ __forceinline__ uint32_t packh2(float a, float b) {
    __half2 h = __floats2half2_rn(a, b);
    uint32_t r; *(__half2*)&r = h; return r;
}
__device__ __forceinline__ void hsplit(float x, __half& hi, __half& lo) {
    hi = __float2half_rn(x);
    lo = __float2half_rn(x - __half2float(hi));
}
__device__ __forceinline__ void hsplit2(float a, float b, uint32_t& hi, uint32_t& lo) {
    __half ha = __float2half_rn(a), hb = __float2half_rn(b);
    float ra = a - __half2float(ha), rb = b - __half2float(hb);
    *(__half2*)&hi = __halves2half2(ha, hb);
    lo = packh2(ra, rb);
}

// ---------------- scratch (device globals) ----------------
__device__ float g_qkv[SEQ * H3];
__device__ __align__(16) __half g_xh[SEQ * HID];
__device__ __align__(16) __half g_wqh[H3 * HID], g_wql[H3 * HID];
__device__ __align__(16) __half g_woh[HID * HID], g_wol[HID * HID];
__device__ __align__(16) __half g_ah[SEQ * HID];
__device__ __align__(16) __half g_qh[NHEAD * SEQ * 64];
__device__ __align__(16) __half g_kh[NHEAD * SEQ * 64], g_kl[NHEAD * SEQ * 64];
__device__ __align__(16) __half g_vth[NHEAD * 64 * SEQ], g_vtl[NHEAD * 64 * SEQ];
__device__ __align__(16) __half g_kgh[NHEAD * 32 * 64], g_kgl[NHEAD * 32 * 64];
__device__ __align__(16) __half g_vtgh[NHEAD * 64 * 32], g_vtgl[NHEAD * 64 * 32];

// ---------------- conversions ----------------
__global__ __launch_bounds__(256) void conv_half(const float* __restrict__ in,
                                                 __half* __restrict__ out, int n4) {
    int i = blockIdx.x * blockDim.x + threadIdx.x;
    if (i >= n4) return;
    float4 v = ((const float4*)in)[i];
    uint32_t* op = (uint32_t*)out;
    op[2 * i]     = packh2(v.x, v.y);
    op[2 * i + 1] = packh2(v.z, v.w);
}
__global__ __launch_bounds__(256) void split_half(const float* __restrict__ in,
                                                  __half* __restrict__ hi,
                                                  __half* __restrict__ lo, int n4) {
    int i = blockIdx.x * blockDim.x + threadIdx.x;
    if (i >= n4) return;
    float4 v = ((const float4*)in)[i];
    uint32_t h0, l0, h1, l1;
    hsplit2(v.x, v.y, h0, l0);
    hsplit2(v.z, v.w, h1, l1);
    uint32_t* hp = (uint32_t*)hi;
    uint32_t* lp = (uint32_t*)lo;
    hp[2 * i] = h0; hp[2 * i + 1] = h1;
    lp[2 * i] = l0; lp[2 * i + 1] = l1;
}

// ---------------- fp16 2-term GEMM: C = A @ (Bh+Bl)^T ----------------
#define SSTR 40
#define BUFE (128 * SSTR)

template<int BM>
__global__ __launch_bounds__(256) void gemm_f16(const __half* __restrict__ Ag,
                                                const __half* __restrict__ Bhg,
                                                const __half* __restrict__ Blg,
                                                float* __restrict__ C,
                                                int M, int N, int K) {
    constexpr int IM = BM / 32;
    constexpr int ABUF = BM * SSTR;
    constexpr int STGE = ABUF + 2 * BUFE;

    extern __shared__ __half smf[];
    const uint32_t sbase = smem_u32(smf);

    const int tid = threadIdx.x;
    const int wid = tid >> 5;
    const int lane = tid & 31;
    const int g = lane >> 2;
    const int t = lane & 3;
    const int warp_m = (wid & 1) * (BM / 2);
    const int warp_n = (wid >> 1) * 32;
    const int tile_m = blockIdx.y * BM;
    const int tile_n = blockIdx.x * 128;

    const int a_row = warp_m + ((lane >> 3) & 1) * 8 + (lane & 7);
    const int a_col = (lane >> 4) * 8;
    const int b_row = warp_n + (lane >> 4) * 8 + (lane & 7);
    const int b_col = ((lane >> 3) & 1) * 8;

    float acc[IM][4][4];
#pragma unroll
    for (int im = 0; im < IM; im++)
#pragma unroll
        for (int jn = 0; jn < 4; jn++)
#pragma unroll
            for (int c = 0; c < 4; c++) acc[im][jn][c] = 0.f;

    auto load_stage = [&](int st, int k0) {
        const uint32_t sb = sbase + (uint32_t)st * STGE * 2;
        for (int idx = tid; idx < BM * 4; idx += 256) {
            const int row = idx >> 2;
            const int c8  = (idx & 3) * 8;
            cp16(sb + (uint32_t)(row * SSTR + c8) * 2,
                 Ag + (size_t)(tile_m + row) * K + k0 + c8);
        }
        for (int idx = tid; idx < 512; idx += 256) {
            const int row = idx >> 2;
            const int c8  = (idx & 3) * 8;
            const uint32_t so = (uint32_t)(row * SSTR + c8) * 2;
            const size_t goB = (size_t)(tile_n + row) * K + k0 + c8;
            cp16(sb + ABUF * 2 + so,          Bhg + goB);
            cp16(sb + (ABUF + BUFE) * 2 + so, Blg + goB);
        }
    };

    const int nchunks = K >> 5;
    load_stage(0, 0);
    CP_COMMIT();

    for (int ch = 0; ch < nchunks; ch++) {
        if (ch + 1 < nchunks) load_stage((ch + 1) & 1, (ch + 1) << 5);
        CP_COMMIT();
        CP_WAIT1();
        __syncthreads();

        const uint32_t sb = sbase + (uint32_t)(ch & 1) * STGE * 2;
#pragma unroll
        for (int ks = 0; ks < 32; ks += 16) {
            uint32_t aH[IM][4];
#pragma unroll
            for (int im = 0; im < IM; im++) {
                const uint32_t ad = sb + (uint32_t)((a_row + im * 16) * SSTR + ks + a_col) * 2;
                ldm_x4(aH[im][0], aH[im][1], aH[im][2], aH[im][3], ad);
            }
#pragma unroll
            for (int jp = 0; jp < 2; jp++) {
                uint32_t bh0, bh1, bh2, bh3, bl0, bl1, bl2, bl3;
                const uint32_t bd = sb + ABUF * 2
                                  + (uint32_t)((b_row + jp * 16) * SSTR + ks + b_col) * 2;
                ldm_x4(bh0, bh1, bh2, bh3, bd);
                ldm_x4(bl0, bl1, bl2, bl3, bd + BUFE * 2);
#pragma unroll
                for (int im = 0; im < IM; im++) {
                    float* a0p = acc[im][2 * jp];
                    float* a1p = acc[im][2 * jp + 1];
                    mma16816h(a0p[0], a0p[1], a0p[2], a0p[3],
                              aH[im][0], aH[im][1], aH[im][2], aH[im][3], bh0, bh1);
                    mma16816h(a1p[0], a1p[1], a1p[2], a1p[3],
                              aH[im][0], aH[im][1], aH[im][2], aH[im][3], bh2, bh3);
                }
#pragma unroll
                for (int im = 0; im < IM; im++) {
                    float* a0p = acc[im][2 * jp];
                    float* a1p = acc[im][2 * jp + 1];
                    mma16816h(a0p[0], a0p[1], a0p[2], a0p[3],
                              aH[im][0], aH[im][1], aH[im][2], aH[im][3], bl0, bl1);
                    mma16816h(a1p[0], a1p[1], a1p[2], a1p[3],
                              aH[im][0], aH[im][1], aH[im][2], aH[im][3], bl2, bl3);
                }
            }
        }
        __syncthreads();
    }

#pragma unroll
    for (int im = 0; im < IM; im++) {
        const int row = tile_m + warp_m + im * 16 + g;
#pragma unroll
        for (int jn = 0; jn < 4; jn++) {
            const int col = tile_n + warp_n + jn * 8 + 2 * t;
            float2 v0; v0.x = acc[im][jn][0]; v0.y = acc[im][jn][1];
            float2 v1; v1.x = acc[im][jn][2]; v1.y = acc[im][jn][3];
            *(float2*)(C + (size_t)row * N + col)       = v0;
            *(float2*)(C + (size_t)(row + 8) * N + col) = v1;
        }
    }
}

#define GF_SMEM128 (2 * (128 * SSTR + 2 * BUFE) * 2)
#define GF_SMEM64  (2 * (64 * SSTR + 2 * BUFE) * 2)

// ---------------- prep: per-head fp16 Q (plain) / K,Vt (hi+lo) ----------------
#define PVS 66
__global__ __launch_bounds__(256) void prep_attn() {
    const int st = blockIdx.x;
    const int h  = blockIdx.y;
    const int s0 = st * 64;
    const int tid = threadIdx.x;

    __shared__ __half vth[64][PVS], vtl[64][PVS];

    for (int idx = tid; idx < 1024; idx += 256) {
        const int r = idx >> 4, c4 = (idx & 15) << 2;
        const size_t base = (size_t)(s0 + r) * H3 + h * HD + c4;
        const size_t qo = (size_t)h * SEQ * 64 + (size_t)(s0 + r) * 64 + c4;
        float4 q = *(const float4*)(g_qkv + base);
        *(uint32_t*)&g_qh[qo]     = packh2(q.x * 0.125f, q.y * 0.125f);
        *(uint32_t*)&g_qh[qo + 2] = packh2(q.z * 0.125f, q.w * 0.125f);
        float4 k = *(const float4*)(g_qkv + base + HID);
        uint32_t h0, l0, h1, l1;
        hsplit2(k.x, k.y, h0, l0);
        hsplit2(k.z, k.w, h1, l1);
        *(uint32_t*)&g_kh[qo] = h0; *(uint32_t*)&g_kh[qo + 2] = h1;
        *(uint32_t*)&g_kl[qo] = l0; *(uint32_t*)&g_kl[qo + 2] = l1;
        float4 v = *(const float4*)(g_qkv + base + 2 * HID);
        hsplit(v.x, vth[c4 + 0][r], vtl[c4 + 0][r]);
        hsplit(v.y, vth[c4 + 1][r], vtl[c4 + 1][r]);
        hsplit(v.z, vth[c4 + 2][r], vtl[c4 + 2][r]);
        hsplit(v.w, vth[c4 + 3][r], vtl[c4 + 3][r]);
    }
    __syncthreads();

    for (int idx = tid; idx < 2048; idx += 256) {
        const int d = idx >> 5, cp = (idx & 31) << 1;
        const size_t vo = (size_t)h * 64 * SEQ + (size_t)d * SEQ + s0 + cp;
        *(uint32_t*)&g_vth[vo] = *(const uint32_t*)&vth[d][cp];
        *(uint32_t*)&g_vtl[vo] = *(const uint32_t*)&vtl[d][cp];
    }
    if (tid < 16) {
        const int c4 = tid * 4;
        float4 k = *(const float4*)(g_qkv + (size_t)s0 * H3 + HID + h * HD + c4);
        uint32_t h0, l0, h1, l1;
        hsplit2(k.x, k.y, h0, l0);
        hsplit2(k.z, k.w, h1, l1);
        const size_t ko = (size_t)h * 32 * 64 + (size_t)st * 64 + c4;
        *(uint32_t*)&g_kgh[ko] = h0; *(uint32_t*)&g_kgh[ko + 2] = h1;
        *(uint32_t*)&g_kgl[ko] = l0; *(uint32_t*)&g_kgl[ko + 2] = l1;
    }
    if (tid < 64) {
        const size_t go = (size_t)h * 64 * 32 + (size_t)tid * 32 + st;
        g_vtgh[go] = vth[tid][0];
        g_vtgl[go] = vtl[tid][0];
    }
}

// ================= MMA attention core (fp16 2-term) =================
#define MASKV (-3.0e38f)
#define ATS   72
#define ATILE (64 * ATS)
#define AT_SMEM ((1 + 8) * ATILE * 2)

template<int NKT, int MODE>
__device__ __forceinline__ void attn_compute(
    uint32_t sKh, uint32_t sVh, int kb, int qr0,
    int t, int brow, int bcol,
    const uint32_t qh[4][4],
    float o[8][4], float& m0, float& m1, float& l0, float& l1)
{
    constexpr int NJ = NKT / 8;
    float sc[NJ][4];

#pragma unroll
    for (int jp = 0; jp < NKT / 16; jp++) {
#pragma unroll
        for (int e = 0; e < 4; e++) { sc[2 * jp][e] = 0.f; sc[2 * jp + 1][e] = 0.f; }
#pragma unroll
        for (int c = 0; c < 4; c++) {
            uint32_t b0, b1, b2, b3, d0, d1, d2, d3;
            const uint32_t ka = sKh + (uint32_t)((jp * 16 + brow) * ATS + c * 16 + bcol) * 2;
            ldm_x4(b0, b1, b2, b3, ka);
            ldm_x4(d0, d1, d2, d3, ka + ATILE * 2);
            float* s0p = sc[2 * jp];
            float* s1p = sc[2 * jp + 1];
            mma16816h(s0p[0], s0p[1], s0p[2], s0p[3],
                      qh[c][0], qh[c][1], qh[c][2], qh[c][3], b0, b1);
            mma16816h(s1p[0], s1p[1], s1p[2], s1p[3],
                      qh[c][0], qh[c][1], qh[c][2], qh[c][3], b2, b3);
            mma16816h(s0p[0], s0p[1], s0p[2], s0p[3],
                      qh[c][0], qh[c][1], qh[c][2], qh[c][3], d0, d1);
            mma16816h(s1p[0], s1p[1], s1p[2], s1p[3],
                      qh[c][0], qh[c][1], qh[c][2], qh[c][3], d2, d3);
        }
    }

    float tm0 = MASKV, tm1 = MASKV;
#pragma unroll
    for (int jn = 0; jn < NJ; jn++) {
#pragma unroll
        for (int e = 0; e < 2; e++) {
            if (MODE < 2) {
                const int ci  = jn * 8 + 2 * t + e;
                const int key = (MODE == 1) ? (ci * GSTRIDE) : (kb + ci);
                int d0 = qr0 - key; d0 = d0 < 0 ? -d0 : d0;
                int d1 = qr0 + 8 - key; d1 = d1 < 0 ? -d1 : d1;
                const bool in0 = (MODE == 1) ? (d0 > WIN) : (d0 <= WIN);
                const bool in1 = (MODE == 1) ? (d1 > WIN) : (d1 <= WIN);
                if (!in0) sc[jn][e]     = MASKV;
                if (!in1) sc[jn][2 + e] = MASKV;
            }
            tm0 = fmaxf(tm0, sc[jn][e]);
            tm1 = fmaxf(tm1, sc[jn][2 + e]);
        }
    }
    tm0 = fmaxf(tm0, __shfl_xor_sync(0xffffffffu, tm0, 1));
    tm0 = fmaxf(tm0, __shfl_xor_sync(0xffffffffu, tm0, 2));
    tm1 = fmaxf(tm1, __shfl_xor_sync(0xffffffffu, tm1, 1));
    tm1 = fmaxf(tm1, __shfl_xor_sync(0xffffffffu, tm1, 2));

    const float mn0 = fmaxf(m0, tm0), mn1 = fmaxf(m1, tm1);
    const float e0 = __expf(m0 - mn0), e1 = __expf(m1 - mn1);
    m0 = mn0; m1 = mn1; l0 *= e0; l1 *= e1;
#pragma unroll
    for (int nb = 0; nb < 8; nb++) {
        o[nb][0] *= e0; o[nb][1] *= e0; o[nb][2] *= e1; o[nb][3] *= e1;
    }

    float s0 = 0.f, s1 = 0.f;
#pragma unroll
    for (int c = 0; c < NKT / 16; c++) {
        const float p00 = __expf(sc[2 * c][0] - m0);
        const float p01 = __expf(sc[2 * c][1] - m0);
        const float p02 = __expf(sc[2 * c][2] - m1);
        const float p03 = __expf(sc[2 * c][3] - m1);
        const float p10 = __expf(sc[2 * c + 1][0] - m0);
        const float p11 = __expf(sc[2 * c + 1][1] - m0);
        const float p12 = __expf(sc[2 * c + 1][2] - m1);
        const float p13 = __expf(sc[2 * c + 1][3] - m1);
        s0 += (p00 + p01) + (p10 + p11);
        s1 += (p02 + p03) + (p12 + p13);
        uint32_t ah[4];
        ah[0] = packh2(p00, p01);
        ah[1] = packh2(p02, p03);
        ah[2] = packh2(p10, p11);
        ah[3] = packh2(p12, p13);
#pragma unroll
        for (int np = 0; np < 4; np++) {
            uint32_t v0, v1, v2, v3, w0, w1, w2, w3;
            const uint32_t va = sVh + (uint32_t)((np * 16 + brow) * ATS + c * 16 + bcol) * 2;
            ldm_x4(v0, v1, v2, v3, va);
            ldm_x4(w0, w1, w2, w3, va + ATILE * 2);
            float* oa = o[2 * np];
            float* ob = o[2 * np + 1];
            mma16816h(oa[0], oa[1], oa[2], oa[3], ah[0], ah[1], ah[2], ah[3], v0, v1);
            mma16816h(ob[0], ob[1], ob[2], ob[3], ah[0], ah[1], ah[2], ah[3], v2, v3);
            mma16816h(oa[0], oa[1], oa[2], oa[3], ah[0], ah[1], ah[2], ah[3], w0, w1);
            mma16816h(ob[0], ob[1], ob[2], ob[3], ah[0], ah[1], ah[2], ah[3], w2, w3);
        }
    }
    s0 += __shfl_xor_sync(0xffffffffu, s0, 1);
    s0 += __shfl_xor_sync(0xffffffffu, s0, 2);
    s1 += __shfl_xor_sync(0xffffffffu, s1, 1);
    s1 += __shfl_xor_sync(0xffffffffu, s1, 2);
    l0 += s0; l1 += s1;
}

// ================= band + global-col attention =================
__global__ __launch_bounds__(128) void attn_mma() {
    extern __shared__ __half sm_[];
    const uint32_t sb = smem_u32(sm_);
    const uint32_t sQ = sb;

    const int qt = blockIdx.x, h = blockIdx.y, q0 = qt * 64;
    const int tid = threadIdx.x, wid = tid >> 5, lane = tid & 31;
    const int g = lane >> 2, t = lane & 3;
    const int brow = ((lane >> 4) << 3) + (lane & 7);
    const int bcol = ((lane >> 3) & 1) * 8;

    {
        const __half* qp = g_qh + (size_t)h * SEQ * 64 + (size_t)q0 * 64;
        for (int idx = tid; idx < 512; idx += 128) {
            const int r = idx >> 3, c = idx & 7;
            cp16(sQ + (uint32_t)(r * ATS + c * 8) * 2, qp + r * 64 + c * 8);
        }
    }
    CP_COMMIT();

    const int kb0 = q0 >= WIN ? q0 - WIN : 0;
    const int kb1 = (q0 + 64 + WIN) <= SEQ ? (q0 + 64 + WIN) : SEQ;
    const int nband = (kb1 - kb0) >> 6;
    const int T = nband + 1;

    auto stage_base = [&](int s) { return sb + (uint32_t)(1 + 4 * s) * ATILE * 2; };
    auto stage_band = [&](int s, int kb) {
        const uint32_t b = stage_base(s);
        const __half* khp = g_kh + (size_t)h * SEQ * 64 + (size_t)kb * 64;
        const __half* klp = g_kl + (size_t)h * SEQ * 64 + (size_t)kb * 64;
        const __half* vhp = g_vth + (size_t)h * 64 * SEQ + kb;
        const __half* vlp = g_vtl + (size_t)h * 64 * SEQ + kb;
        for (int idx = tid; idx < 512; idx += 128) {
            const int r = idx >> 3, c = idx & 7;
            const uint32_t so = (uint32_t)(r * ATS + c * 8) * 2;
            cp16(b + so,                 khp + r * 64 + c * 8);
            cp16(b + ATILE * 2 + so,     klp + r * 64 + c * 8);
            cp16(b + 2 * ATILE * 2 + so, vhp + (size_t)r * SEQ + c * 8);
            cp16(b + 3 * ATILE * 2 + so, vlp + (size_t)r * SEQ + c * 8);
        }
    };
    auto stage_glob = [&](int s) {
        const uint32_t b = stage_base(s);
        const __half* khp = g_kgh + (size_t)h * 32 * 64;
        const __half* klp = g_kgl + (size_t)h * 32 * 64;
        const __half* vhp = g_vtgh + (size_t)h * 64 * 32;
        const __half* vlp = g_vtgl + (size_t)h * 64 * 32;
        for (int idx = tid; idx < 256; idx += 128) {
            const int r = idx >> 3, c = idx & 7;
            const uint32_t so = (uint32_t)(r * ATS + c * 8) * 2;
            cp16(b + so,             khp + r * 64 + c * 8);
            cp16(b + ATILE * 2 + so, klp + r * 64 + c * 8);
        }
        for (int idx = tid; idx < 256; idx += 128) {
            const int r = idx >> 2, c = idx & 3;
            const uint32_t so = (uint32_t)(r * ATS + c * 8) * 2;
            cp16(b + 2 * ATILE * 2 + so, vhp + r * 32 + c * 8);
            cp16(b + 3 * ATILE * 2 + so, vlp + r * 32 + c * 8);
        }
    };

    stage_band(0, kb0);
    CP_COMMIT();
    CP_WAIT1();
    __syncthreads();

    uint32_t qh[4][4];
    {
        const int ar = wid * 16 + ((lane >> 3) & 1) * 8 + (lane & 7);
        const int ac = (lane >> 4) * 8;
#pragma unroll
        for (int c = 0; c < 4; c++) {
            const uint32_t ad = sQ + (uint32_t)(ar * ATS + c * 16 + ac) * 2;
            ldm_x4(qh[c][0], qh[c][1], qh[c][2], qh[c][3], ad);
        }
    }

    float o[8][4];
#pragma unroll
    for (int nb = 0; nb < 8; nb++)
#pragma unroll
        for (int c = 0; c < 4; c++) o[nb][c] = 0.f;
    float m0 = -1e30f, m1 = -1e30f, l0 = 0.f, l1 = 0.f;
    const int qr0 = q0 + wid * 16 + g;

    for (int i = 0; i < T; i++) {
        if (i + 1 < T) {
            if (i + 1 < nband) stage_band((i + 1) & 1, kb0 + (i + 1) * 64);
            else stage_glob((i + 1) & 1);
            CP_COMMIT();
            CP_WAIT1();
        } else {
            CP_WAIT0();
        }
        __syncthreads();
        const uint32_t b = stage_base(i & 1);
        if (i < nband)
            attn_compute<64, 0>(b, b + 2 * ATILE * 2, kb0 + i * 64, qr0,
                                t, brow, bcol, qh, o, m0, m1, l0, l1);
        else
            attn_compute<32, 1>(b, b + 2 * ATILE * 2, 0, qr0,
                                t, brow, bcol, qh, o, m0, m1, l0, l1);
        __syncthreads();
    }

    const float i0 = 1.f / l0, i1 = 1.f / l1;
    const int row0 = q0 + wid * 16 + g;
#pragma unroll
    for (int nb = 0; nb < 8; nb++) {
        const size_t ofs0 = (size_t)row0 * HID + h * HD + nb * 8 + 2 * t;
        const size_t ofs1 = ofs0 + (size_t)8 * HID;
        *(uint32_t*)&g_ah[ofs0] = packh2(o[nb][0] * i0, o[nb][1] * i0);
        *(uint32_t*)&g_ah[ofs1] = packh2(o[nb][2] * i1, o[nb][3] * i1);
    }
}

// ================= global rows: MMA over all 2048 keys =================
#define GA_QSZ   (32 * ATS * 2)
#define GA_TILES (2 * 2 * 4 * ATILE * 2)
#define GA_OBUF  (2 * 16 * 64 * 4)
#define GA_SMEM  (GA_QSZ + GA_TILES + GA_OBUF + 256)

__global__ __launch_bounds__(128) void attn_global_mma() {
    extern __shared__ __half smg2[];
    const uint32_t sb = smem_u32(smg2);
    const int h = blockIdx.x;
    const int tid = threadIdx.x, wid = tid >> 5, lane = tid & 31;
    const int g = lane >> 2, t = lane & 3;
    const int rh = wid & 1, kp = wid >> 1;
    const int brow = ((lane >> 4) << 3) + (lane & 7);
    const int bcol = ((lane >> 3) & 1) * 8;

    const uint32_t sQ = sb;
    const uint32_t tiles0 = sb + GA_QSZ;
    float* obuf = (float*)(smg2 + (32 * ATS + 16 * ATILE));
    float* slm  = obuf + 2 * 16 * 64;
    float* sll  = slm + 32;

    {
        const __half* qp = g_qh + (size_t)h * SEQ * 64;
        for (int idx = tid; idx < 256; idx += 128) {
            const int r = idx >> 3, c = idx & 7;
            cp16(sQ + (uint32_t)(r * ATS + c * 8) * 2, qp + (size_t)r * 64 * 64 + c * 8);
        }
    }
    CP_COMMIT();

    auto stage_tiles = [&](int st, int it) {
#pragma unroll
        for (int kpi = 0; kpi < 2; kpi++) {
            const int kt = (it * 2 + kpi) * 64;
            const uint32_t b = tiles0 + (uint32_t)((st * 2 + kpi) * 4) * ATILE * 2;
            const __half* khp = g_kh + (size_t)h * SEQ * 64 + (size_t)kt * 64;
            const __half* klp = g_kl + (size_t)h * SEQ * 64 + (size_t)kt * 64;
            const __half* vhp = g_vth + (size_t)h * 64 * SEQ + kt;
            const __half* vlp = g_vtl + (size_t)h * 64 * SEQ + kt;
            for (int idx = tid; idx < 512; idx += 128) {
                const int r = idx >> 3, c = idx & 7;
                const uint32_t so = (uint32_t)(r * ATS + c * 8) * 2;
                cp16(b + so,                 khp + r * 64 + c * 8);
                cp16(b + ATILE * 2 + so,     klp + r * 64 + c * 8);
                cp16(b + 2 * ATILE * 2 + so, vhp + (size_t)r * SEQ + c * 8);
                cp16(b + 3 * ATILE * 2 + so, vlp + (size_t)r * SEQ + c * 8);
            }
        }
    };

    stage_tiles(0, 0);
    CP_COMMIT();
    CP_WAIT1();
    __syncthreads();

    uint32_t qh[4][4];
    {
        const int ar = rh * 16 + ((lane >> 3) & 1) * 8 + (lane & 7);
        const int ac = (lane >> 4) * 8;
#pragma unroll
        for (int c = 0; c < 4; c++) {
            const uint32_t ad = sQ + (uint32_t)(ar * ATS + c * 16 + ac) * 2;
            ldm_x4(qh[c][0], qh[c][1], qh[c][2], qh[c][3], ad);
        }
    }

    float o[8][4];
#pragma unroll
    for (int nb = 0; nb < 8; nb++)
#pragma unroll
        for (int c = 0; c < 4; c++) o[nb][c] = 0.f;
    float m0 = -1e30f, m1 = -1e30f, l0 = 0.f, l1 = 0.f;

    for (int it = 0; it < 16; it++) {
        if (it + 1 < 16) {
            stage_tiles((it + 1) & 1, it + 1);
            CP_COMMIT();
            CP_WAIT1();
        } else {
            CP_WAIT0();
        }
        __syncthreads();
        const uint32_t b = tiles0 + (uint32_t)(((it & 1) * 2 + kp) * 4) * ATILE * 2;
        attn_compute<64, 2>(b, b + 2 * ATILE * 2, 0, 0,
                            t, brow, bcol, qh, o, m0, m1, l0, l1);
        __syncthreads();
    }

    __syncthreads();
    if (kp == 1) {
        float* ob = obuf + rh * 16 * 64;
#pragma unroll
        for (int nb = 0; nb < 8; nb++) {
            ob[g * 64 + nb * 8 + 2 * t]           = o[nb][0];
            ob[g * 64 + nb * 8 + 2 * t + 1]       = o[nb][1];
            ob[(g + 8) * 64 + nb * 8 + 2 * t]     = o[nb][2];
            ob[(g + 8) * 64 + nb * 8 + 2 * t + 1] = o[nb][3];
        }
        if (t == 0) {
            slm[rh * 16 + g] = m0; slm[rh * 16 + g + 8] = m1;
            sll[rh * 16 + g] = l0; sll[rh * 16 + g + 8] = l1;
        }
    }
    __syncthreads();
    if (kp == 0) {
        const float pm0 = slm[rh * 16 + g], pm1 = slm[rh * 16 + g + 8];
        const float pl0 = sll[rh * 16 + g], pl1 = sll[rh * 16 + g + 8];
        const float M0 = fmaxf(m0, pm0), M1 = fmaxf(m1, pm1);
        const float e0 = __expf(m0 - M0), f0 = __expf(pm0 - M0);
        const float e1 = __expf(m1 - M1), f1 = __expf(pm1 - M1);
        const float L0 = l0 * e0 + pl0 * f0;
        const float L1 = l1 * e1 + pl1 * f1;
        const float i0 = 1.f / L0, i1 = 1.f / L1;
        float* ob = obuf + rh * 16 * 64;
        const int qi0 = (rh * 16 + g) * 64;
        const int qi1 = (rh * 16 + g + 8) * 64;
#pragma unroll
        for (int nb = 0; nb < 8; nb++) {
            const int cc = nb * 8 + 2 * t;
            const float r00 = (o[nb][0] * e0 + ob[g * 64 + cc] * f0) * i0;
            const float r01 = (o[nb][1] * e0 + ob[g * 64 + cc + 1] * f0) * i0;
            const float r10 = (o[nb][2] * e1 + ob[(g + 8) * 64 + cc] * f1) * i1;
            const float r11 = (o[nb][3] * e1 + ob[(g + 8) * 64 + cc + 1] * f1) * i1;
            const size_t ofs0 = (size_t)qi0 * HID + h * HD + cc;
            const size_t ofs1 = (size_t)qi1 * HID + h * HD + cc;
            *(uint32_t*)&g_ah[ofs0] = packh2(r00, r01);
            *(uint32_t*)&g_ah[ofs1] = packh2(r10, r11);
        }
    }
}

// ---------------- launch: forked-stream DAG ----------------
// Streams/events are created ONCE, on the first (correctness, non-captured)
// call, and reused for the capture call. They are never destroyed, so no
// allocation/free happens during or after graph capture — the pre-capture
// memory baseline already includes them. The issued kernel DAG is identical
// on every call (deterministic work).
static cudaStream_t g_s1 = nullptr, g_s2 = nullptr;
static cudaEvent_t  g_eFork, g_eX, g_eWo, g_ePrep, g_eG;

extern "C" void kernel_launch(void* const* d_in, const int* in_sizes, int n_in,
                              void* d_out, int out_size) {
    const float* x    = (const float*)d_in[0];
    const float* Wqkv = (const float*)d_in[1];
    const float* Wout = (const float*)d_in[2];
    float* out = (float*)d_out;

    float* qkv = nullptr;
    cudaGetSymbolAddress((void**)&qkv, g_qkv);
    __half *xh, *wqh, *wql, *woh, *wol, *ah;
    cudaGetSymbolAddress((void**)&xh,  g_xh);
    cudaGetSymbolAddress((void**)&wqh, g_wqh); cudaGetSymbolAddress((void**)&wql, g_wql);
    cudaGetSymbolAddress((void**)&woh, g_woh); cudaGetSymbolAddress((void**)&wol, g_wol);
    cudaGetSymbolAddress((void**)&ah,  g_ah);

    if (g_s1 == nullptr) {
        cudaStreamCreateWithFlags(&g_s1, cudaStreamNonBlocking);
        cudaStreamCreateWithFlags(&g_s2, cudaStreamNonBlocking);
        cudaEventCreateWithFlags(&g_eFork, cudaEventDisableTiming);
        cudaEventCreateWithFlags(&g_eX,    cudaEventDisableTiming);
        cudaEventCreateWithFlags(&g_eWo,   cudaEventDisableTiming);
        cudaEventCreateWithFlags(&g_ePrep, cudaEventDisableTiming);
        cudaEventCreateWithFlags(&g_eG,    cudaEventDisableTiming);
        cudaFuncSetAttribute(gemm_f16<128>, cudaFuncAttributeMaxDynamicSharedMemorySize, GF_SMEM128);
        cudaFuncSetAttribute(gemm_f16<64>,  cudaFuncAttributeMaxDynamicSharedMemorySize, GF_SMEM64);
        cudaFuncSetAttribute(attn_mma, cudaFuncAttributeMaxDynamicSharedMemorySize, AT_SMEM);
        cudaFuncSetAttribute(attn_global_mma, cudaFuncAttributeMaxDynamicSharedMemorySize, GA_SMEM);
    }

    // fork s1 off the (capture) default stream
    cudaEventRecord(g_eFork, 0);
    cudaStreamWaitEvent(g_s1, g_eFork, 0);

    // s1: x -> fp16, then Wout split (latter only needed by final GEMM)
    conv_half<<<(SEQ * HID / 4 + 255) / 256, 256, 0, g_s1>>>(x, xh, SEQ * HID / 4);
    cudaEventRecord(g_eX, g_s1);
    split_half<<<(HID * HID / 4 + 255) / 256, 256, 0, g_s1>>>(Wout, woh, wol, HID * HID / 4);
    cudaEventRecord(g_eWo, g_s1);

    // default: Wqkv split, then QKV GEMM (needs xh from s1)
    split_half<<<(H3 * HID / 4 + 255) / 256, 256>>>(Wqkv, wqh, wql, H3 * HID / 4);
    cudaStreamWaitEvent(0, g_eX, 0);
    gemm_f16<128><<<dim3(H3 / 128, SEQ / 128), 256, GF_SMEM128>>>(xh, wqh, wql, qkv, SEQ, H3, HID);

    // default: per-head fp16 operands
    prep_attn<<<dim3(SEQ / 64, NHEAD), 256>>>();
    cudaEventRecord(g_ePrep, 0);

    // s2: global-row attention in parallel with banded attention
    cudaStreamWaitEvent(g_s2, g_ePrep, 0);
    attn_global_mma<<<NHEAD, 128, GA_SMEM, g_s2>>>();
    cudaEventRecord(g_eG, g_s2);

    // default: banded attention
    attn_mma<<<dim3(SEQ / 64, NHEAD), 128, AT_SMEM>>>();

    // join everything, then out-projection
    cudaStreamWaitEvent(0, g_eG, 0);
    cudaStreamWaitEvent(0, g_eWo, 0);
    gemm_f16<64><<<dim3(HID / 128, SEQ / 64), 256, GF_SMEM64>>>(ah, woh, wol, out, SEQ, HID, HID);
}

// round 15
// speedup vs baseline: 1.3861x; 1.2051x over previous
#include <cuda_runtime.h>
#include <cuda_fp16.h>
#include <cstdint>

// ---------------- problem constants ----------------
#define SEQ   2048
#define HID   1024
#define H3    3072
#define NHEAD 16
#define HD    64
#define WIN   128
#define GSTRIDE 64

// ---------------- mma / ldmatrix / cp.async helpers ----------------
__device__ __forceinline__ void mma16816h(float& c0, float& c1, float& c2, float& c3,
                                          uint32_t a0, uint32_t a1, uint32_t a2, uint32_t a3,
                                          uint32_t b0, uint32_t b1) {
    asm volatile(
        "mma.sync.aligned.m16n8k16.row.col.f32.f16.f16.f32 "
        "{%0,%1,%2,%3}, {%4,%5,%6,%7}, {%8,%9}, {%0,%1,%2,%3};"
        : "+f"(c0), "+f"(c1), "+f"(c2), "+f"(c3)
        : "r"(a0), "r"(a1), "r"(a2), "r"(a3), "r"(b0), "r"(b1));
}
__device__ __forceinline__ void ldm_x4(uint32_t& r0, uint32_t& r1, uint32_t& r2, uint32_t& r3,
                                       uint32_t addr) {
    asm volatile("ldmatrix.sync.aligned.m8n8.x4.shared.b16 {%0,%1,%2,%3}, [%4];"
                 : "=r"(r0), "=r"(r1), "=r"(r2), "=r"(r3) : "r"(addr));
}
__device__ __forceinline__ uint32_t smem_u32(const void* p) {
    uint32_t a;
    asm("{ .reg .u64 t; cvta.to.shared.u64 t, %1; cvt.u32.u64 %0, t; }" : "=r"(a) : "l"(p));
    return a;
}
__device__ __forceinline__ void cp16(uint32_t saddr, const void* gptr) {
    asm volatile("cp.async.cg.shared.global [%0], [%1], 16;" :: "r"(saddr), "l"(gptr));
}
#define CP_COMMIT() asm volatile("cp.async.commit_group;" ::: "memory")
#define CP_WAIT1()  asm volatile("cp.async.wait_group 1;" ::: "memory")
#define CP_WAIT0()  asm volatile("cp.async.wait_group 0;" ::: "memory")

// fp16 helpers
__device__ __forceinline__ uint32_t packh2(float a, float b) {
    __half2 h = __floats2half2_rn(a, b);
    uint32_t r; *(__half2*)&r = h; return r;
}
__device__ __forceinline__ void hsplit(float x, __half& hi, __half& lo) {
    hi = __float2half_rn(x);
    lo = __float2half_rn(x - __half2float(hi));
}
__device__ __forceinline__ void hsplit2(float a, float b, uint32_t& hi, uint32_t& lo) {
    __half ha = __float2half_rn(a), hb = __float2half_rn(b);
    float ra = a - __half2float(ha), rb = b - __half2float(hb);
    *(__half2*)&hi = __halves2half2(ha, hb);
    lo = packh2(ra, rb);
}

// ---------------- scratch (device globals) ----------------
__device__ float g_qkv[SEQ * H3];
__device__ __align__(16) __half g_xh[SEQ * HID];
__device__ __align__(16) __half g_wqh[H3 * HID];
__device__ __align__(16) __half g_woh[HID * HID], g_wol[HID * HID];
__device__ __align__(16) __half g_ah[SEQ * HID];
__device__ __align__(16) __half g_qh[NHEAD * SEQ * 64];
__device__ __align__(16) __half g_kh[NHEAD * SEQ * 64], g_kl[NHEAD * SEQ * 64];
__device__ __align__(16) __half g_vth[NHEAD * 64 * SEQ], g_vtl[NHEAD * 64 * SEQ];
__device__ __align__(16) __half g_kgh[NHEAD * 32 * 64], g_kgl[NHEAD * 32 * 64];
__device__ __align__(16) __half g_vtgh[NHEAD * 64 * 32], g_vtgl[NHEAD * 64 * 32];

// ---------------- conversions ----------------
__global__ __launch_bounds__(256) void conv_half(const float* __restrict__ in,
                                                 __half* __restrict__ out, int n4) {
    int i = blockIdx.x * blockDim.x + threadIdx.x;
    if (i >= n4) return;
    float4 v = ((const float4*)in)[i];
    uint32_t* op = (uint32_t*)out;
    op[2 * i]     = packh2(v.x, v.y);
    op[2 * i + 1] = packh2(v.z, v.w);
}
__global__ __launch_bounds__(256) void split_half(const float* __restrict__ in,
                                                  __half* __restrict__ hi,
                                                  __half* __restrict__ lo, int n4) {
    int i = blockIdx.x * blockDim.x + threadIdx.x;
    if (i >= n4) return;
    float4 v = ((const float4*)in)[i];
    uint32_t h0, l0, h1, l1;
    hsplit2(v.x, v.y, h0, l0);
    hsplit2(v.z, v.w, h1, l1);
    uint32_t* hp = (uint32_t*)hi;
    uint32_t* lp = (uint32_t*)lo;
    hp[2 * i] = h0; hp[2 * i + 1] = h1;
    lp[2 * i] = l0; lp[2 * i + 1] = l1;
}

#define SSTR 40
#define BUFE (128 * SSTR)

// ---------------- plain fp16 GEMM: C = A @ B^T (1 MMA term) ----------------
__global__ __launch_bounds__(256) void gemm_f16p(const __half* __restrict__ Ag,
                                                 const __half* __restrict__ Bg,
                                                 float* __restrict__ C,
                                                 int M, int N, int K) {
    constexpr int STGE = 2 * BUFE;  // A(128x40) + B(128x40)

    extern __shared__ __half smf[];
    const uint32_t sbase = smem_u32(smf);

    const int tid = threadIdx.x;
    const int wid = tid >> 5;
    const int lane = tid & 31;
    const int g = lane >> 2;
    const int t = lane & 3;
    const int warp_m = (wid & 1) * 64;
    const int warp_n = (wid >> 1) * 32;
    const int tile_m = blockIdx.y * 128;
    const int tile_n = blockIdx.x * 128;

    const int a_row = warp_m + ((lane >> 3) & 1) * 8 + (lane & 7);
    const int a_col = (lane >> 4) * 8;
    const int b_row = warp_n + (lane >> 4) * 8 + (lane & 7);
    const int b_col = ((lane >> 3) & 1) * 8;

    float acc[4][4][4];
#pragma unroll
    for (int im = 0; im < 4; im++)
#pragma unroll
        for (int jn = 0; jn < 4; jn++)
#pragma unroll
            for (int c = 0; c < 4; c++) acc[im][jn][c] = 0.f;

    auto load_stage = [&](int st, int k0) {
        const uint32_t sb = sbase + (uint32_t)st * STGE * 2;
#pragma unroll
        for (int rep = 0; rep < 2; rep++) {
            const int idx = tid + 256 * rep;
            const int row = idx >> 2;
            const int c8  = (idx & 3) * 8;
            const uint32_t so = (uint32_t)(row * SSTR + c8) * 2;
            cp16(sb + so,            Ag + (size_t)(tile_m + row) * K + k0 + c8);
            cp16(sb + BUFE * 2 + so, Bg + (size_t)(tile_n + row) * K + k0 + c8);
        }
    };

    const int nchunks = K >> 5;
    load_stage(0, 0);
    CP_COMMIT();

    for (int ch = 0; ch < nchunks; ch++) {
        if (ch + 1 < nchunks) load_stage((ch + 1) & 1, (ch + 1) << 5);
        CP_COMMIT();
        CP_WAIT1();
        __syncthreads();

        const uint32_t sb = sbase + (uint32_t)(ch & 1) * STGE * 2;
#pragma unroll
        for (int ks = 0; ks < 32; ks += 16) {
            uint32_t aH[4][4];
#pragma unroll
            for (int im = 0; im < 4; im++) {
                const uint32_t ad = sb + (uint32_t)((a_row + im * 16) * SSTR + ks + a_col) * 2;
                ldm_x4(aH[im][0], aH[im][1], aH[im][2], aH[im][3], ad);
            }
#pragma unroll
            for (int jp = 0; jp < 2; jp++) {
                uint32_t bh0, bh1, bh2, bh3;
                const uint32_t bd = sb + BUFE * 2
                                  + (uint32_t)((b_row + jp * 16) * SSTR + ks + b_col) * 2;
                ldm_x4(bh0, bh1, bh2, bh3, bd);
#pragma unroll
                for (int im = 0; im < 4; im++) {
                    float* a0p = acc[im][2 * jp];
                    float* a1p = acc[im][2 * jp + 1];
                    mma16816h(a0p[0], a0p[1], a0p[2], a0p[3],
                              aH[im][0], aH[im][1], aH[im][2], aH[im][3], bh0, bh1);
                    mma16816h(a1p[0], a1p[1], a1p[2], a1p[3],
                              aH[im][0], aH[im][1], aH[im][2], aH[im][3], bh2, bh3);
                }
            }
        }
        __syncthreads();
    }

#pragma unroll
    for (int im = 0; im < 4; im++) {
        const int row = tile_m + warp_m + im * 16 + g;
#pragma unroll
        for (int jn = 0; jn < 4; jn++) {
            const int col = tile_n + warp_n + jn * 8 + 2 * t;
            float2 v0; v0.x = acc[im][jn][0]; v0.y = acc[im][jn][1];
            float2 v1; v1.x = acc[im][jn][2]; v1.y = acc[im][jn][3];
            *(float2*)(C + (size_t)row * N + col)       = v0;
            *(float2*)(C + (size_t)(row + 8) * N + col) = v1;
        }
    }
}
#define GFP_SMEM (2 * 2 * BUFE * 2)

// ---------------- fp16 2-term GEMM: C = A @ (Bh+Bl)^T (out-proj) ----------------
template<int BM>
__global__ __launch_bounds__(256) void gemm_f16(const __half* __restrict__ Ag,
                                                const __half* __restrict__ Bhg,
                                                const __half* __restrict__ Blg,
                                                float* __restrict__ C,
                                                int M, int N, int K) {
    constexpr int IM = BM / 32;
    constexpr int ABUF = BM * SSTR;
    constexpr int STGE = ABUF + 2 * BUFE;

    extern __shared__ __half smf[];
    const uint32_t sbase = smem_u32(smf);

    const int tid = threadIdx.x;
    const int wid = tid >> 5;
    const int lane = tid & 31;
    const int g = lane >> 2;
    const int t = lane & 3;
    const int warp_m = (wid & 1) * (BM / 2);
    const int warp_n = (wid >> 1) * 32;
    const int tile_m = blockIdx.y * BM;
    const int tile_n = blockIdx.x * 128;

    const int a_row = warp_m + ((lane >> 3) & 1) * 8 + (lane & 7);
    const int a_col = (lane >> 4) * 8;
    const int b_row = warp_n + (lane >> 4) * 8 + (lane & 7);
    const int b_col = ((lane >> 3) & 1) * 8;

    float acc[IM][4][4];
#pragma unroll
    for (int im = 0; im < IM; im++)
#pragma unroll
        for (int jn = 0; jn < 4; jn++)
#pragma unroll
            for (int c = 0; c < 4; c++) acc[im][jn][c] = 0.f;

    auto load_stage = [&](int st, int k0) {
        const uint32_t sb = sbase + (uint32_t)st * STGE * 2;
        for (int idx = tid; idx < BM * 4; idx += 256) {
            const int row = idx >> 2;
            const int c8  = (idx & 3) * 8;
            cp16(sb + (uint32_t)(row * SSTR + c8) * 2,
                 Ag + (size_t)(tile_m + row) * K + k0 + c8);
        }
        for (int idx = tid; idx < 512; idx += 256) {
            const int row = idx >> 2;
            const int c8  = (idx & 3) * 8;
            const uint32_t so = (uint32_t)(row * SSTR + c8) * 2;
            const size_t goB = (size_t)(tile_n + row) * K + k0 + c8;
            cp16(sb + ABUF * 2 + so,          Bhg + goB);
            cp16(sb + (ABUF + BUFE) * 2 + so, Blg + goB);
        }
    };

    const int nchunks = K >> 5;
    load_stage(0, 0);
    CP_COMMIT();

    for (int ch = 0; ch < nchunks; ch++) {
        if (ch + 1 < nchunks) load_stage((ch + 1) & 1, (ch + 1) << 5);
        CP_COMMIT();
        CP_WAIT1();
        __syncthreads();

        const uint32_t sb = sbase + (uint32_t)(ch & 1) * STGE * 2;
#pragma unroll
        for (int ks = 0; ks < 32; ks += 16) {
            uint32_t aH[IM][4];
#pragma unroll
            for (int im = 0; im < IM; im++) {
                const uint32_t ad = sb + (uint32_t)((a_row + im * 16) * SSTR + ks + a_col) * 2;
                ldm_x4(aH[im][0], aH[im][1], aH[im][2], aH[im][3], ad);
            }
#pragma unroll
            for (int jp = 0; jp < 2; jp++) {
                uint32_t bh0, bh1, bh2, bh3, bl0, bl1, bl2, bl3;
                const uint32_t bd = sb + ABUF * 2
                                  + (uint32_t)((b_row + jp * 16) * SSTR + ks + b_col) * 2;
                ldm_x4(bh0, bh1, bh2, bh3, bd);
                ldm_x4(bl0, bl1, bl2, bl3, bd + BUFE * 2);
#pragma unroll
                for (int im = 0; im < IM; im++) {
                    float* a0p = acc[im][2 * jp];
                    float* a1p = acc[im][2 * jp + 1];
                    mma16816h(a0p[0], a0p[1], a0p[2], a0p[3],
                              aH[im][0], aH[im][1], aH[im][2], aH[im][3], bh0, bh1);
                    mma16816h(a1p[0], a1p[1], a1p[2], a1p[3],
                              aH[im][0], aH[im][1], aH[im][2], aH[im][3], bh2, bh3);
                }
#pragma unroll
                for (int im = 0; im < IM; im++) {
                    float* a0p = acc[im][2 * jp];
                    float* a1p = acc[im][2 * jp + 1];
                    mma16816h(a0p[0], a0p[1], a0p[2], a0p[3],
                              aH[im][0], aH[im][1], aH[im][2], aH[im][3], bl0, bl1);
                    mma16816h(a1p[0], a1p[1], a1p[2], a1p[3],
                              aH[im][0], aH[im][1], aH[im][2], aH[im][3], bl2, bl3);
                }
            }
        }
        __syncthreads();
    }

#pragma unroll
    for (int im = 0; im < IM; im++) {
        const int row = tile_m + warp_m + im * 16 + g;
#pragma unroll
        for (int jn = 0; jn < 4; jn++) {
            const int col = tile_n + warp_n + jn * 8 + 2 * t;
            float2 v0; v0.x = acc[im][jn][0]; v0.y = acc[im][jn][1];
            float2 v1; v1.x = acc[im][jn][2]; v1.y = acc[im][jn][3];
            *(float2*)(C + (size_t)row * N + col)       = v0;
            *(float2*)(C + (size_t)(row + 8) * N + col) = v1;
        }
    }
}
#define GF_SMEM64 (2 * (64 * SSTR + 2 * BUFE) * 2)

// ---------------- prep: per-head fp16 Q (plain) / K,Vt (hi+lo) ----------------
#define PVS 66
__global__ __launch_bounds__(256) void prep_attn() {
    const int st = blockIdx.x;
    const int h  = blockIdx.y;
    const int s0 = st * 64;
    const int tid = threadIdx.x;

    __shared__ __half vth[64][PVS], vtl[64][PVS];

    for (int idx = tid; idx < 1024; idx += 256) {
        const int r = idx >> 4, c4 = (idx & 15) << 2;
        const size_t base = (size_t)(s0 + r) * H3 + h * HD + c4;
        const size_t qo = (size_t)h * SEQ * 64 + (size_t)(s0 + r) * 64 + c4;
        float4 q = *(const float4*)(g_qkv + base);
        *(uint32_t*)&g_qh[qo]     = packh2(q.x * 0.125f, q.y * 0.125f);
        *(uint32_t*)&g_qh[qo + 2] = packh2(q.z * 0.125f, q.w * 0.125f);
        float4 k = *(const float4*)(g_qkv + base + HID);
        uint32_t h0, l0, h1, l1;
        hsplit2(k.x, k.y, h0, l0);
        hsplit2(k.z, k.w, h1, l1);
        *(uint32_t*)&g_kh[qo] = h0; *(uint32_t*)&g_kh[qo + 2] = h1;
        *(uint32_t*)&g_kl[qo] = l0; *(uint32_t*)&g_kl[qo + 2] = l1;
        float4 v = *(const float4*)(g_qkv + base + 2 * HID);
        hsplit(v.x, vth[c4 + 0][r], vtl[c4 + 0][r]);
        hsplit(v.y, vth[c4 + 1][r], vtl[c4 + 1][r]);
        hsplit(v.z, vth[c4 + 2][r], vtl[c4 + 2][r]);
        hsplit(v.w, vth[c4 + 3][r], vtl[c4 + 3][r]);
    }
    __syncthreads();

    for (int idx = tid; idx < 2048; idx += 256) {
        const int d = idx >> 5, cp = (idx & 31) << 1;
        const size_t vo = (size_t)h * 64 * SEQ + (size_t)d * SEQ + s0 + cp;
        *(uint32_t*)&g_vth[vo] = *(const uint32_t*)&vth[d][cp];
        *(uint32_t*)&g_vtl[vo] = *(const uint32_t*)&vtl[d][cp];
    }
    if (tid < 16) {
        const int c4 = tid * 4;
        float4 k = *(const float4*)(g_qkv + (size_t)s0 * H3 + HID + h * HD + c4);
        uint32_t h0, l0, h1, l1;
        hsplit2(k.x, k.y, h0, l0);
        hsplit2(k.z, k.w, h1, l1);
        const size_t ko = (size_t)h * 32 * 64 + (size_t)st * 64 + c4;
        *(uint32_t*)&g_kgh[ko] = h0; *(uint32_t*)&g_kgh[ko + 2] = h1;
        *(uint32_t*)&g_kgl[ko] = l0; *(uint32_t*)&g_kgl[ko + 2] = l1;
    }
    if (tid < 64) {
        const size_t go = (size_t)h * 64 * 32 + (size_t)tid * 32 + st;
        g_vtgh[go] = vth[tid][0];
        g_vtgl[go] = vtl[tid][0];
    }
}

// ================= MMA attention core (fp16 2-term) =================
#define MASKV (-3.0e38f)
#define ATS   72
#define ATILE (64 * ATS)
#define AT_SMEM ((1 + 8) * ATILE * 2)

template<int NKT, int MODE>
__device__ __forceinline__ void attn_compute(
    uint32_t sKh, uint32_t sVh, int kb, int qr0,
    int t, int brow, int bcol,
    const uint32_t qh[4][4],
    float o[8][4], float& m0, float& m1, float& l0, float& l1)
{
    constexpr int NJ = NKT / 8;
    float sc[NJ][4];

#pragma unroll
    for (int jp = 0; jp < NKT / 16; jp++) {
#pragma unroll
        for (int e = 0; e < 4; e++) { sc[2 * jp][e] = 0.f; sc[2 * jp + 1][e] = 0.f; }
#pragma unroll
        for (int c = 0; c < 4; c++) {
            uint32_t b0, b1, b2, b3, d0, d1, d2, d3;
            const uint32_t ka = sKh + (uint32_t)((jp * 16 + brow) * ATS + c * 16 + bcol) * 2;
            ldm_x4(b0, b1, b2, b3, ka);
            ldm_x4(d0, d1, d2, d3, ka + ATILE * 2);
            float* s0p = sc[2 * jp];
            float* s1p = sc[2 * jp + 1];
            mma16816h(s0p[0], s0p[1], s0p[2], s0p[3],
                      qh[c][0], qh[c][1], qh[c][2], qh[c][3], b0, b1);
            mma16816h(s1p[0], s1p[1], s1p[2], s1p[3],
                      qh[c][0], qh[c][1], qh[c][2], qh[c][3], b2, b3);
            mma16816h(s0p[0], s0p[1], s0p[2], s0p[3],
                      qh[c][0], qh[c][1], qh[c][2], qh[c][3], d0, d1);
            mma16816h(s1p[0], s1p[1], s1p[2], s1p[3],
                      qh[c][0], qh[c][1], qh[c][2], qh[c][3], d2, d3);
        }
    }

    float tm0 = MASKV, tm1 = MASKV;
#pragma unroll
    for (int jn = 0; jn < NJ; jn++) {
#pragma unroll
        for (int e = 0; e < 2; e++) {
            if (MODE < 2) {
                const int ci  = jn * 8 + 2 * t + e;
                const int key = (MODE == 1) ? (ci * GSTRIDE) : (kb + ci);
                int d0 = qr0 - key; d0 = d0 < 0 ? -d0 : d0;
                int d1 = qr0 + 8 - key; d1 = d1 < 0 ? -d1 : d1;
                const bool in0 = (MODE == 1) ? (d0 > WIN) : (d0 <= WIN);
                const bool in1 = (MODE == 1) ? (d1 > WIN) : (d1 <= WIN);
                if (!in0) sc[jn][e]     = MASKV;
                if (!in1) sc[jn][2 + e] = MASKV;
            }
            tm0 = fmaxf(tm0, sc[jn][e]);
            tm1 = fmaxf(tm1, sc[jn][2 + e]);
        }
    }
    tm0 = fmaxf(tm0, __shfl_xor_sync(0xffffffffu, tm0, 1));
    tm0 = fmaxf(tm0, __shfl_xor_sync(0xffffffffu, tm0, 2));
    tm1 = fmaxf(tm1, __shfl_xor_sync(0xffffffffu, tm1, 1));
    tm1 = fmaxf(tm1, __shfl_xor_sync(0xffffffffu, tm1, 2));

    const float mn0 = fmaxf(m0, tm0), mn1 = fmaxf(m1, tm1);
    const float e0 = __expf(m0 - mn0), e1 = __expf(m1 - mn1);
    m0 = mn0; m1 = mn1; l0 *= e0; l1 *= e1;
#pragma unroll
    for (int nb = 0; nb < 8; nb++) {
        o[nb][0] *= e0; o[nb][1] *= e0; o[nb][2] *= e1; o[nb][3] *= e1;
    }

    float s0 = 0.f, s1 = 0.f;
#pragma unroll
    for (int c = 0; c < NKT / 16; c++) {
        const float p00 = __expf(sc[2 * c][0] - m0);
        const float p01 = __expf(sc[2 * c][1] - m0);
        const float p02 = __expf(sc[2 * c][2] - m1);
        const float p03 = __expf(sc[2 * c][3] - m1);
        const float p10 = __expf(sc[2 * c + 1][0] - m0);
        const float p11 = __expf(sc[2 * c + 1][1] - m0);
        const float p12 = __expf(sc[2 * c + 1][2] - m1);
        const float p13 = __expf(sc[2 * c + 1][3] - m1);
        s0 += (p00 + p01) + (p10 + p11);
        s1 += (p02 + p03) + (p12 + p13);
        uint32_t ah[4];
        ah[0] = packh2(p00, p01);
        ah[1] = packh2(p02, p03);
        ah[2] = packh2(p10, p11);
        ah[3] = packh2(p12, p13);
#pragma unroll
        for (int np = 0; np < 4; np++) {
            uint32_t v0, v1, v2, v3, w0, w1, w2, w3;
            const uint32_t va = sVh + (uint32_t)((np * 16 + brow) * ATS + c * 16 + bcol) * 2;
            ldm_x4(v0, v1, v2, v3, va);
            ldm_x4(w0, w1, w2, w3, va + ATILE * 2);
            float* oa = o[2 * np];
            float* ob = o[2 * np + 1];
            mma16816h(oa[0], oa[1], oa[2], oa[3], ah[0], ah[1], ah[2], ah[3], v0, v1);
            mma16816h(ob[0], ob[1], ob[2], ob[3], ah[0], ah[1], ah[2], ah[3], v2, v3);
            mma16816h(oa[0], oa[1], oa[2], oa[3], ah[0], ah[1], ah[2], ah[3], w0, w1);
            mma16816h(ob[0], ob[1], ob[2], ob[3], ah[0], ah[1], ah[2], ah[3], w2, w3);
        }
    }
    s0 += __shfl_xor_sync(0xffffffffu, s0, 1);
    s0 += __shfl_xor_sync(0xffffffffu, s0, 2);
    s1 += __shfl_xor_sync(0xffffffffu, s1, 1);
    s1 += __shfl_xor_sync(0xffffffffu, s1, 2);
    l0 += s0; l1 += s1;
}

// ================= band + global-col attention =================
__global__ __launch_bounds__(128) void attn_mma() {
    extern __shared__ __half sm_[];
    const uint32_t sb = smem_u32(sm_);
    const uint32_t sQ = sb;

    const int qt = blockIdx.x, h = blockIdx.y, q0 = qt * 64;
    const int tid = threadIdx.x, wid = tid >> 5, lane = tid & 31;
    const int g = lane >> 2, t = lane & 3;
    const int brow = ((lane >> 4) << 3) + (lane & 7);
    const int bcol = ((lane >> 3) & 1) * 8;

    {
        const __half* qp = g_qh + (size_t)h * SEQ * 64 + (size_t)q0 * 64;
        for (int idx = tid; idx < 512; idx += 128) {
            const int r = idx >> 3, c = idx & 7;
            cp16(sQ + (uint32_t)(r * ATS + c * 8) * 2, qp + r * 64 + c * 8);
        }
    }
    CP_COMMIT();

    const int kb0 = q0 >= WIN ? q0 - WIN : 0;
    const int kb1 = (q0 + 64 + WIN) <= SEQ ? (q0 + 64 + WIN) : SEQ;
    const int nband = (kb1 - kb0) >> 6;
    const int T = nband + 1;

    auto stage_base = [&](int s) { return sb + (uint32_t)(1 + 4 * s) * ATILE * 2; };
    auto stage_band = [&](int s, int kb) {
        const uint32_t b = stage_base(s);
        const __half* khp = g_kh + (size_t)h * SEQ * 64 + (size_t)kb * 64;
        const __half* klp = g_kl + (size_t)h * SEQ * 64 + (size_t)kb * 64;
        const __half* vhp = g_vth + (size_t)h * 64 * SEQ + kb;
        const __half* vlp = g_vtl + (size_t)h * 64 * SEQ + kb;
        for (int idx = tid; idx < 512; idx += 128) {
            const int r = idx >> 3, c = idx & 7;
            const uint32_t so = (uint32_t)(r * ATS + c * 8) * 2;
            cp16(b + so,                 khp + r * 64 + c * 8);
            cp16(b + ATILE * 2 + so,     klp + r * 64 + c * 8);
            cp16(b + 2 * ATILE * 2 + so, vhp + (size_t)r * SEQ + c * 8);
            cp16(b + 3 * ATILE * 2 + so, vlp + (size_t)r * SEQ + c * 8);
        }
    };
    auto stage_glob = [&](int s) {
        const uint32_t b = stage_base(s);
        const __half* khp = g_kgh + (size_t)h * 32 * 64;
        const __half* klp = g_kgl + (size_t)h * 32 * 64;
        const __half* vhp = g_vtgh + (size_t)h * 64 * 32;
        const __half* vlp = g_vtgl + (size_t)h * 64 * 32;
        for (int idx = tid; idx < 256; idx += 128) {
            const int r = idx >> 3, c = idx & 7;
            const uint32_t so = (uint32_t)(r * ATS + c * 8) * 2;
            cp16(b + so,             khp + r * 64 + c * 8);
            cp16(b + ATILE * 2 + so, klp + r * 64 + c * 8);
        }
        for (int idx = tid; idx < 256; idx += 128) {
            const int r = idx >> 2, c = idx & 3;
            const uint32_t so = (uint32_t)(r * ATS + c * 8) * 2;
            cp16(b + 2 * ATILE * 2 + so, vhp + r * 32 + c * 8);
            cp16(b + 3 * ATILE * 2 + so, vlp + r * 32 + c * 8);
        }
    };

    stage_band(0, kb0);
    CP_COMMIT();
    CP_WAIT1();
    __syncthreads();

    uint32_t qh[4][4];
    {
        const int ar = wid * 16 + ((lane >> 3) & 1) * 8 + (lane & 7);
        const int ac = (lane >> 4) * 8;
#pragma unroll
        for (int c = 0; c < 4; c++) {
            const uint32_t ad = sQ + (uint32_t)(ar * ATS + c * 16 + ac) * 2;
            ldm_x4(qh[c][0], qh[c][1], qh[c][2], qh[c][3], ad);
        }
    }

    float o[8][4];
#pragma unroll
    for (int nb = 0; nb < 8; nb++)
#pragma unroll
        for (int c = 0; c < 4; c++) o[nb][c] = 0.f;
    float m0 = -1e30f, m1 = -1e30f, l0 = 0.f, l1 = 0.f;
    const int qr0 = q0 + wid * 16 + g;

    for (int i = 0; i < T; i++) {
        if (i + 1 < T) {
            if (i + 1 < nband) stage_band((i + 1) & 1, kb0 + (i + 1) * 64);
            else stage_glob((i + 1) & 1);
            CP_COMMIT();
            CP_WAIT1();
        } else {
            CP_WAIT0();
        }
        __syncthreads();
        const uint32_t b = stage_base(i & 1);
        if (i < nband)
            attn_compute<64, 0>(b, b + 2 * ATILE * 2, kb0 + i * 64, qr0,
                                t, brow, bcol, qh, o, m0, m1, l0, l1);
        else
            attn_compute<32, 1>(b, b + 2 * ATILE * 2, 0, qr0,
                                t, brow, bcol, qh, o, m0, m1, l0, l1);
        __syncthreads();
    }

    const float i0 = 1.f / l0, i1 = 1.f / l1;
    const int row0 = q0 + wid * 16 + g;
#pragma unroll
    for (int nb = 0; nb < 8; nb++) {
        const size_t ofs0 = (size_t)row0 * HID + h * HD + nb * 8 + 2 * t;
        const size_t ofs1 = ofs0 + (size_t)8 * HID;
        *(uint32_t*)&g_ah[ofs0] = packh2(o[nb][0] * i0, o[nb][1] * i0);
        *(uint32_t*)&g_ah[ofs1] = packh2(o[nb][2] * i1, o[nb][3] * i1);
    }
}

// ================= global rows: MMA over all 2048 keys =================
#define GA_QSZ   (32 * ATS * 2)
#define GA_TILES (2 * 2 * 4 * ATILE * 2)
#define GA_OBUF  (2 * 16 * 64 * 4)
#define GA_SMEM  (GA_QSZ + GA_TILES + GA_OBUF + 256)

__global__ __launch_bounds__(128) void attn_global_mma() {
    extern __shared__ __half smg2[];
    const uint32_t sb = smem_u32(smg2);
    const int h = blockIdx.x;
    const int tid = threadIdx.x, wid = tid >> 5, lane = tid & 31;
    const int g = lane >> 2, t = lane & 3;
    const int rh = wid & 1, kp = wid >> 1;
    const int brow = ((lane >> 4) << 3) + (lane & 7);
    const int bcol = ((lane >> 3) & 1) * 8;

    const uint32_t sQ = sb;
    const uint32_t tiles0 = sb + GA_QSZ;
    float* obuf = (float*)(smg2 + (32 * ATS + 16 * ATILE));
    float* slm  = obuf + 2 * 16 * 64;
    float* sll  = slm + 32;

    {
        const __half* qp = g_qh + (size_t)h * SEQ * 64;
        for (int idx = tid; idx < 256; idx += 128) {
            const int r = idx >> 3, c = idx & 7;
            cp16(sQ + (uint32_t)(r * ATS + c * 8) * 2, qp + (size_t)r * 64 * 64 + c * 8);
        }
    }
    CP_COMMIT();

    auto stage_tiles = [&](int st, int it) {
#pragma unroll
        for (int kpi = 0; kpi < 2; kpi++) {
            const int kt = (it * 2 + kpi) * 64;
            const uint32_t b = tiles0 + (uint32_t)((st * 2 + kpi) * 4) * ATILE * 2;
            const __half* khp = g_kh + (size_t)h * SEQ * 64 + (size_t)kt * 64;
            const __half* klp = g_kl + (size_t)h * SEQ * 64 + (size_t)kt * 64;
            const __half* vhp = g_vth + (size_t)h * 64 * SEQ + kt;
            const __half* vlp = g_vtl + (size_t)h * 64 * SEQ + kt;
            for (int idx = tid; idx < 512; idx += 128) {
                const int r = idx >> 3, c = idx & 7;
                const uint32_t so = (uint32_t)(r * ATS + c * 8) * 2;
                cp16(b + so,                 khp + r * 64 + c * 8);
                cp16(b + ATILE * 2 + so,     klp + r * 64 + c * 8);
                cp16(b + 2 * ATILE * 2 + so, vhp + (size_t)r * SEQ + c * 8);
                cp16(b + 3 * ATILE * 2 + so, vlp + (size_t)r * SEQ + c * 8);
            }
        }
    };

    stage_tiles(0, 0);
    CP_COMMIT();
    CP_WAIT1();
    __syncthreads();

    uint32_t qh[4][4];
    {
        const int ar = rh * 16 + ((lane >> 3) & 1) * 8 + (lane & 7);
        const int ac = (lane >> 4) * 8;
#pragma unroll
        for (int c = 0; c < 4; c++) {
            const uint32_t ad = sQ + (uint32_t)(ar * ATS + c * 16 + ac) * 2;
            ldm_x4(qh[c][0], qh[c][1], qh[c][2], qh[c][3], ad);
        }
    }

    float o[8][4];
#pragma unroll
    for (int nb = 0; nb < 8; nb++)
#pragma unroll
        for (int c = 0; c < 4; c++) o[nb][c] = 0.f;
    float m0 = -1e30f, m1 = -1e30f, l0 = 0.f, l1 = 0.f;

    for (int it = 0; it < 16; it++) {
        if (it + 1 < 16) {
            stage_tiles((it + 1) & 1, it + 1);
            CP_COMMIT();
            CP_WAIT1();
        } else {
            CP_WAIT0();
        }
        __syncthreads();
        const uint32_t b = tiles0 + (uint32_t)(((it & 1) * 2 + kp) * 4) * ATILE * 2;
        attn_compute<64, 2>(b, b + 2 * ATILE * 2, 0, 0,
                            t, brow, bcol, qh, o, m0, m1, l0, l1);
        __syncthreads();
    }

    __syncthreads();
    if (kp == 1) {
        float* ob = obuf + rh * 16 * 64;
#pragma unroll
        for (int nb = 0; nb < 8; nb++) {
            ob[g * 64 + nb * 8 + 2 * t]           = o[nb][0];
            ob[g * 64 + nb * 8 + 2 * t + 1]       = o[nb][1];
            ob[(g + 8) * 64 + nb * 8 + 2 * t]     = o[nb][2];
            ob[(g + 8) * 64 + nb * 8 + 2 * t + 1] = o[nb][3];
        }
        if (t == 0) {
            slm[rh * 16 + g] = m0; slm[rh * 16 + g + 8] = m1;
            sll[rh * 16 + g] = l0; sll[rh * 16 + g + 8] = l1;
        }
    }
    __syncthreads();
    if (kp == 0) {
        const float pm0 = slm[rh * 16 + g], pm1 = slm[rh * 16 + g + 8];
        const float pl0 = sll[rh * 16 + g], pl1 = sll[rh * 16 + g + 8];
        const float M0 = fmaxf(m0, pm0), M1 = fmaxf(m1, pm1);
        const float e0 = __expf(m0 - M0), f0 = __expf(pm0 - M0);
        const float e1 = __expf(m1 - M1), f1 = __expf(pm1 - M1);
        const float L0 = l0 * e0 + pl0 * f0;
        const float L1 = l1 * e1 + pl1 * f1;
        const float i0 = 1.f / L0, i1 = 1.f / L1;
        float* ob = obuf + rh * 16 * 64;
        const int qi0 = (rh * 16 + g) * 64;
        const int qi1 = (rh * 16 + g + 8) * 64;
#pragma unroll
        for (int nb = 0; nb < 8; nb++) {
            const int cc = nb * 8 + 2 * t;
            const float r00 = (o[nb][0] * e0 + ob[g * 64 + cc] * f0) * i0;
            const float r01 = (o[nb][1] * e0 + ob[g * 64 + cc + 1] * f0) * i0;
            const float r10 = (o[nb][2] * e1 + ob[(g + 8) * 64 + cc] * f1) * i1;
            const float r11 = (o[nb][3] * e1 + ob[(g + 8) * 64 + cc + 1] * f1) * i1;
            const size_t ofs0 = (size_t)qi0 * HID + h * HD + cc;
            const size_t ofs1 = (size_t)qi1 * HID + h * HD + cc;
            *(uint32_t*)&g_ah[ofs0] = packh2(r00, r01);
            *(uint32_t*)&g_ah[ofs1] = packh2(r10, r11);
        }
    }
}

// ---------------- launch: forked-stream DAG (lazy-init handles) ----------------
static cudaStream_t g_s1 = nullptr, g_s2 = nullptr;
static cudaEvent_t  g_eFork, g_eX, g_eWo, g_ePrep, g_eG;

extern "C" void kernel_launch(void* const* d_in, const int* in_sizes, int n_in,
                              void* d_out, int out_size) {
    const float* x    = (const float*)d_in[0];
    const float* Wqkv = (const float*)d_in[1];
    const float* Wout = (const float*)d_in[2];
    float* out = (float*)d_out;

    float* qkv = nullptr;
    cudaGetSymbolAddress((void**)&qkv, g_qkv);
    __half *xh, *wqh, *woh, *wol, *ah;
    cudaGetSymbolAddress((void**)&xh,  g_xh);
    cudaGetSymbolAddress((void**)&wqh, g_wqh);
    cudaGetSymbolAddress((void**)&woh, g_woh); cudaGetSymbolAddress((void**)&wol, g_wol);
    cudaGetSymbolAddress((void**)&ah,  g_ah);

    if (g_s1 == nullptr) {
        cudaStreamCreateWithFlags(&g_s1, cudaStreamNonBlocking);
        cudaStreamCreateWithFlags(&g_s2, cudaStreamNonBlocking);
        cudaEventCreateWithFlags(&g_eFork, cudaEventDisableTiming);
        cudaEventCreateWithFlags(&g_eX,    cudaEventDisableTiming);
        cudaEventCreateWithFlags(&g_eWo,   cudaEventDisableTiming);
        cudaEventCreateWithFlags(&g_ePrep, cudaEventDisableTiming);
        cudaEventCreateWithFlags(&g_eG,    cudaEventDisableTiming);
        cudaFuncSetAttribute(gemm_f16p,    cudaFuncAttributeMaxDynamicSharedMemorySize, GFP_SMEM);
        cudaFuncSetAttribute(gemm_f16<64>, cudaFuncAttributeMaxDynamicSharedMemorySize, GF_SMEM64);
        cudaFuncSetAttribute(attn_mma, cudaFuncAttributeMaxDynamicSharedMemorySize, AT_SMEM);
        cudaFuncSetAttribute(attn_global_mma, cudaFuncAttributeMaxDynamicSharedMemorySize, GA_SMEM);
    }

    // fork s1 off the (capture) default stream
    cudaEventRecord(g_eFork, 0);
    cudaStreamWaitEvent(g_s1, g_eFork, 0);

    // s1: x -> fp16, then Wout split (only needed by final GEMM)
    conv_half<<<(SEQ * HID / 4 + 255) / 256, 256, 0, g_s1>>>(x, xh, SEQ * HID / 4);
    cudaEventRecord(g_eX, g_s1);
    split_half<<<(HID * HID / 4 + 255) / 256, 256, 0, g_s1>>>(Wout, woh, wol, HID * HID / 4);
    cudaEventRecord(g_eWo, g_s1);

    // default: Wqkv -> plain fp16, then QKV GEMM (plain fp16, 1 MMA term)
    conv_half<<<(H3 * HID / 4 + 255) / 256, 256>>>(Wqkv, wqh, H3 * HID / 4);
    cudaStreamWaitEvent(0, g_eX, 0);
    gemm_f16p<<<dim3(H3 / 128, SEQ / 128), 256, GFP_SMEM>>>(xh, wqh, qkv, SEQ, H3, HID);

    // default: per-head fp16 operands
    prep_attn<<<dim3(SEQ / 64, NHEAD), 256>>>();
    cudaEventRecord(g_ePrep, 0);

    // s2: global-row attention in parallel with banded attention
    cudaStreamWaitEvent(g_s2, g_ePrep, 0);
    attn_global_mma<<<NHEAD, 128, GA_SMEM, g_s2>>>();
    cudaEventRecord(g_eG, g_s2);

    // default: banded attention
    attn_mma<<<dim3(SEQ / 64, NHEAD), 128, AT_SMEM>>>();

    // join everything, then out-projection (2-term)
    cudaStreamWaitEvent(0, g_eG, 0);
    cudaStreamWaitEvent(0, g_eWo, 0);
    gemm_f16<64><<<dim3(HID / 128, SEQ / 64), 256, GF_SMEM64>>>(ah, woh, wol, out, SEQ, HID, HID);
}

// round 16
// speedup vs baseline: 1.4955x; 1.0789x over previous
#include <cuda_runtime.h>
#include <cuda_fp16.h>
#include <cstdint>

// ---------------- problem constants ----------------
#define SEQ   2048
#define HID   1024
#define H3    3072
#define NHEAD 16
#define HD    64
#define WIN   128
#define GSTRIDE 64

// ---------------- mma / ldmatrix / cp.async helpers ----------------
__device__ __forceinline__ void mma16816h(float& c0, float& c1, float& c2, float& c3,
                                          uint32_t a0, uint32_t a1, uint32_t a2, uint32_t a3,
                                          uint32_t b0, uint32_t b1) {
    asm volatile(
        "mma.sync.aligned.m16n8k16.row.col.f32.f16.f16.f32 "
        "{%0,%1,%2,%3}, {%4,%5,%6,%7}, {%8,%9}, {%0,%1,%2,%3};"
        : "+f"(c0), "+f"(c1), "+f"(c2), "+f"(c3)
        : "r"(a0), "r"(a1), "r"(a2), "r"(a3), "r"(b0), "r"(b1));
}
__device__ __forceinline__ void ldm_x4(uint32_t& r0, uint32_t& r1, uint32_t& r2, uint32_t& r3,
                                       uint32_t addr) {
    asm volatile("ldmatrix.sync.aligned.m8n8.x4.shared.b16 {%0,%1,%2,%3}, [%4];"
                 : "=r"(r0), "=r"(r1), "=r"(r2), "=r"(r3) : "r"(addr));
}
__device__ __forceinline__ uint32_t smem_u32(const void* p) {
    uint32_t a;
    asm("{ .reg .u64 t; cvta.to.shared.u64 t, %1; cvt.u32.u64 %0, t; }" : "=r"(a) : "l"(p));
    return a;
}
__device__ __forceinline__ void cp16(uint32_t saddr, const void* gptr) {
    asm volatile("cp.async.cg.shared.global [%0], [%1], 16;" :: "r"(saddr), "l"(gptr));
}
#define CP_COMMIT() asm volatile("cp.async.commit_group;" ::: "memory")
#define CP_WAIT1()  asm volatile("cp.async.wait_group 1;" ::: "memory")
#define CP_WAIT0()  asm volatile("cp.async.wait_group 0;" ::: "memory")

// fp16 helpers
__device__ __forceinline__ uint32_t packh2(float a, float b) {
    __half2 h = __floats2half2_rn(a, b);
    uint32_t r; *(__half2*)&r = h; return r;
}
__device__ __forceinline__ void hsplit2(float a, float b, uint32_t& hi, uint32_t& lo) {
    __half ha = __float2half_rn(a), hb = __float2half_rn(b);
    float ra = a - __half2float(ha), rb = b - __half2float(hb);
    *(__half2*)&hi = __halves2half2(ha, hb);
    lo = packh2(ra, rb);
}

// ---------------- scratch (device globals) ----------------
__device__ float g_qkv[SEQ * H3];
__device__ __align__(16) __half g_xh[SEQ * HID];
__device__ __align__(16) __half g_wqh[H3 * HID];
__device__ __align__(16) __half g_woh[HID * HID], g_wol[HID * HID];
__device__ __align__(16) __half g_ah[SEQ * HID];
__device__ __align__(16) __half g_qh[NHEAD * SEQ * 64];
__device__ __align__(16) __half g_kh[NHEAD * SEQ * 64];
__device__ __align__(16) __half g_vth[NHEAD * 64 * SEQ];
__device__ __align__(16) __half g_kgh[NHEAD * 32 * 64];
__device__ __align__(16) __half g_vtgh[NHEAD * 64 * 32];

// ---------------- conversions ----------------
__global__ __launch_bounds__(256) void conv_half(const float* __restrict__ in,
                                                 __half* __restrict__ out, int n4) {
    int i = blockIdx.x * blockDim.x + threadIdx.x;
    if (i >= n4) return;
    float4 v = ((const float4*)in)[i];
    uint32_t* op = (uint32_t*)out;
    op[2 * i]     = packh2(v.x, v.y);
    op[2 * i + 1] = packh2(v.z, v.w);
}
__global__ __launch_bounds__(256) void split_half(const float* __restrict__ in,
                                                  __half* __restrict__ hi,
                                                  __half* __restrict__ lo, int n4) {
    int i = blockIdx.x * blockDim.x + threadIdx.x;
    if (i >= n4) return;
    float4 v = ((const float4*)in)[i];
    uint32_t h0, l0, h1, l1;
    hsplit2(v.x, v.y, h0, l0);
    hsplit2(v.z, v.w, h1, l1);
    uint32_t* hp = (uint32_t*)hi;
    uint32_t* lp = (uint32_t*)lo;
    hp[2 * i] = h0; hp[2 * i + 1] = h1;
    lp[2 * i] = l0; lp[2 * i + 1] = l1;
}

#define SSTR 40
#define BUFE (128 * SSTR)

// ---------------- plain fp16 GEMM: C = A @ B^T ----------------
__global__ __launch_bounds__(256) void gemm_f16p(const __half* __restrict__ Ag,
                                                 const __half* __restrict__ Bg,
                                                 float* __restrict__ C,
                                                 int M, int N, int K) {
    constexpr int STGE = 2 * BUFE;

    extern __shared__ __half smf[];
    const uint32_t sbase = smem_u32(smf);

    const int tid = threadIdx.x;
    const int wid = tid >> 5;
    const int lane = tid & 31;
    const int g = lane >> 2;
    const int t = lane & 3;
    const int warp_m = (wid & 1) * 64;
    const int warp_n = (wid >> 1) * 32;
    const int tile_m = blockIdx.y * 128;
    const int tile_n = blockIdx.x * 128;

    const int a_row = warp_m + ((lane >> 3) & 1) * 8 + (lane & 7);
    const int a_col = (lane >> 4) * 8;
    const int b_row = warp_n + (lane >> 4) * 8 + (lane & 7);
    const int b_col = ((lane >> 3) & 1) * 8;

    float acc[4][4][4];
#pragma unroll
    for (int im = 0; im < 4; im++)
#pragma unroll
        for (int jn = 0; jn < 4; jn++)
#pragma unroll
            for (int c = 0; c < 4; c++) acc[im][jn][c] = 0.f;

    auto load_stage = [&](int st, int k0) {
        const uint32_t sb = sbase + (uint32_t)st * STGE * 2;
#pragma unroll
        for (int rep = 0; rep < 2; rep++) {
            const int idx = tid + 256 * rep;
            const int row = idx >> 2;
            const int c8  = (idx & 3) * 8;
            const uint32_t so = (uint32_t)(row * SSTR + c8) * 2;
            cp16(sb + so,            Ag + (size_t)(tile_m + row) * K + k0 + c8);
            cp16(sb + BUFE * 2 + so, Bg + (size_t)(tile_n + row) * K + k0 + c8);
        }
    };

    const int nchunks = K >> 5;
    load_stage(0, 0);
    CP_COMMIT();

    for (int ch = 0; ch < nchunks; ch++) {
        if (ch + 1 < nchunks) load_stage((ch + 1) & 1, (ch + 1) << 5);
        CP_COMMIT();
        CP_WAIT1();
        __syncthreads();

        const uint32_t sb = sbase + (uint32_t)(ch & 1) * STGE * 2;
#pragma unroll
        for (int ks = 0; ks < 32; ks += 16) {
            uint32_t aH[4][4];
#pragma unroll
            for (int im = 0; im < 4; im++) {
                const uint32_t ad = sb + (uint32_t)((a_row + im * 16) * SSTR + ks + a_col) * 2;
                ldm_x4(aH[im][0], aH[im][1], aH[im][2], aH[im][3], ad);
            }
#pragma unroll
            for (int jp = 0; jp < 2; jp++) {
                uint32_t bh0, bh1, bh2, bh3;
                const uint32_t bd = sb + BUFE * 2
                                  + (uint32_t)((b_row + jp * 16) * SSTR + ks + b_col) * 2;
                ldm_x4(bh0, bh1, bh2, bh3, bd);
#pragma unroll
                for (int im = 0; im < 4; im++) {
                    float* a0p = acc[im][2 * jp];
                    float* a1p = acc[im][2 * jp + 1];
                    mma16816h(a0p[0], a0p[1], a0p[2], a0p[3],
                              aH[im][0], aH[im][1], aH[im][2], aH[im][3], bh0, bh1);
                    mma16816h(a1p[0], a1p[1], a1p[2], a1p[3],
                              aH[im][0], aH[im][1], aH[im][2], aH[im][3], bh2, bh3);
                }
            }
        }
        __syncthreads();
    }

#pragma unroll
    for (int im = 0; im < 4; im++) {
        const int row = tile_m + warp_m + im * 16 + g;
#pragma unroll
        for (int jn = 0; jn < 4; jn++) {
            const int col = tile_n + warp_n + jn * 8 + 2 * t;
            float2 v0; v0.x = acc[im][jn][0]; v0.y = acc[im][jn][1];
            float2 v1; v1.x = acc[im][jn][2]; v1.y = acc[im][jn][3];
            *(float2*)(C + (size_t)row * N + col)       = v0;
            *(float2*)(C + (size_t)(row + 8) * N + col) = v1;
        }
    }
}
#define GFP_SMEM (2 * 2 * BUFE * 2)

// ---------------- fp16 2-term GEMM (out-proj) ----------------
template<int BM>
__global__ __launch_bounds__(256) void gemm_f16(const __half* __restrict__ Ag,
                                                const __half* __restrict__ Bhg,
                                                const __half* __restrict__ Blg,
                                                float* __restrict__ C,
                                                int M, int N, int K) {
    constexpr int IM = BM / 32;
    constexpr int ABUF = BM * SSTR;
    constexpr int STGE = ABUF + 2 * BUFE;

    extern __shared__ __half smf[];
    const uint32_t sbase = smem_u32(smf);

    const int tid = threadIdx.x;
    const int wid = tid >> 5;
    const int lane = tid & 31;
    const int g = lane >> 2;
    const int t = lane & 3;
    const int warp_m = (wid & 1) * (BM / 2);
    const int warp_n = (wid >> 1) * 32;
    const int tile_m = blockIdx.y * BM;
    const int tile_n = blockIdx.x * 128;

    const int a_row = warp_m + ((lane >> 3) & 1) * 8 + (lane & 7);
    const int a_col = (lane >> 4) * 8;
    const int b_row = warp_n + (lane >> 4) * 8 + (lane & 7);
    const int b_col = ((lane >> 3) & 1) * 8;

    float acc[IM][4][4];
#pragma unroll
    for (int im = 0; im < IM; im++)
#pragma unroll
        for (int jn = 0; jn < 4; jn++)
#pragma unroll
            for (int c = 0; c < 4; c++) acc[im][jn][c] = 0.f;

    auto load_stage = [&](int st, int k0) {
        const uint32_t sb = sbase + (uint32_t)st * STGE * 2;
        for (int idx = tid; idx < BM * 4; idx += 256) {
            const int row = idx >> 2;
            const int c8  = (idx & 3) * 8;
            cp16(sb + (uint32_t)(row * SSTR + c8) * 2,
                 Ag + (size_t)(tile_m + row) * K + k0 + c8);
        }
        for (int idx = tid; idx < 512; idx += 256) {
            const int row = idx >> 2;
            const int c8  = (idx & 3) * 8;
            const uint32_t so = (uint32_t)(row * SSTR + c8) * 2;
            const size_t goB = (size_t)(tile_n + row) * K + k0 + c8;
            cp16(sb + ABUF * 2 + so,          Bhg + goB);
            cp16(sb + (ABUF + BUFE) * 2 + so, Blg + goB);
        }
    };

    const int nchunks = K >> 5;
    load_stage(0, 0);
    CP_COMMIT();

    for (int ch = 0; ch < nchunks; ch++) {
        if (ch + 1 < nchunks) load_stage((ch + 1) & 1, (ch + 1) << 5);
        CP_COMMIT();
        CP_WAIT1();
        __syncthreads();

        const uint32_t sb = sbase + (uint32_t)(ch & 1) * STGE * 2;
#pragma unroll
        for (int ks = 0; ks < 32; ks += 16) {
            uint32_t aH[IM][4];
#pragma unroll
            for (int im = 0; im < IM; im++) {
                const uint32_t ad = sb + (uint32_t)((a_row + im * 16) * SSTR + ks + a_col) * 2;
                ldm_x4(aH[im][0], aH[im][1], aH[im][2], aH[im][3], ad);
            }
#pragma unroll
            for (int jp = 0; jp < 2; jp++) {
                uint32_t bh0, bh1, bh2, bh3, bl0, bl1, bl2, bl3;
                const uint32_t bd = sb + ABUF * 2
                                  + (uint32_t)((b_row + jp * 16) * SSTR + ks + b_col) * 2;
                ldm_x4(bh0, bh1, bh2, bh3, bd);
                ldm_x4(bl0, bl1, bl2, bl3, bd + BUFE * 2);
#pragma unroll
                for (int im = 0; im < IM; im++) {
                    float* a0p = acc[im][2 * jp];
                    float* a1p = acc[im][2 * jp + 1];
                    mma16816h(a0p[0], a0p[1], a0p[2], a0p[3],
                              aH[im][0], aH[im][1], aH[im][2], aH[im][3], bh0, bh1);
                    mma16816h(a1p[0], a1p[1], a1p[2], a1p[3],
                              aH[im][0], aH[im][1], aH[im][2], aH[im][3], bh2, bh3);
                }
#pragma unroll
                for (int im = 0; im < IM; im++) {
                    float* a0p = acc[im][2 * jp];
                    float* a1p = acc[im][2 * jp + 1];
                    mma16816h(a0p[0], a0p[1], a0p[2], a0p[3],
                              aH[im][0], aH[im][1], aH[im][2], aH[im][3], bl0, bl1);
                    mma16816h(a1p[0], a1p[1], a1p[2], a1p[3],
                              aH[im][0], aH[im][1], aH[im][2], aH[im][3], bl2, bl3);
                }
            }
        }
        __syncthreads();
    }

#pragma unroll
    for (int im = 0; im < IM; im++) {
        const int row = tile_m + warp_m + im * 16 + g;
#pragma unroll
        for (int jn = 0; jn < 4; jn++) {
            const int col = tile_n + warp_n + jn * 8 + 2 * t;
            float2 v0; v0.x = acc[im][jn][0]; v0.y = acc[im][jn][1];
            float2 v1; v1.x = acc[im][jn][2]; v1.y = acc[im][jn][3];
            *(float2*)(C + (size_t)row * N + col)       = v0;
            *(float2*)(C + (size_t)(row + 8) * N + col) = v1;
        }
    }
}
#define GF_SMEM64 (2 * (64 * SSTR + 2 * BUFE) * 2)

// ---------------- prep: per-head plain fp16 Q (scaled), K, Vt ----------------
#define PVS 66
__global__ __launch_bounds__(256) void prep_attn() {
    const int st = blockIdx.x;
    const int h  = blockIdx.y;
    const int s0 = st * 64;
    const int tid = threadIdx.x;

    __shared__ __half vth[64][PVS];

    for (int idx = tid; idx < 1024; idx += 256) {
        const int r = idx >> 4, c4 = (idx & 15) << 2;
        const size_t base = (size_t)(s0 + r) * H3 + h * HD + c4;
        const size_t qo = (size_t)h * SEQ * 64 + (size_t)(s0 + r) * 64 + c4;
        float4 q = *(const float4*)(g_qkv + base);
        *(uint32_t*)&g_qh[qo]     = packh2(q.x * 0.125f, q.y * 0.125f);
        *(uint32_t*)&g_qh[qo + 2] = packh2(q.z * 0.125f, q.w * 0.125f);
        float4 k = *(const float4*)(g_qkv + base + HID);
        *(uint32_t*)&g_kh[qo]     = packh2(k.x, k.y);
        *(uint32_t*)&g_kh[qo + 2] = packh2(k.z, k.w);
        float4 v = *(const float4*)(g_qkv + base + 2 * HID);
        vth[c4 + 0][r] = __float2half_rn(v.x);
        vth[c4 + 1][r] = __float2half_rn(v.y);
        vth[c4 + 2][r] = __float2half_rn(v.z);
        vth[c4 + 3][r] = __float2half_rn(v.w);
    }
    __syncthreads();

    for (int idx = tid; idx < 2048; idx += 256) {
        const int d = idx >> 5, cp = (idx & 31) << 1;
        const size_t vo = (size_t)h * 64 * SEQ + (size_t)d * SEQ + s0 + cp;
        *(uint32_t*)&g_vth[vo] = *(const uint32_t*)&vth[d][cp];
    }
    if (tid < 16) {
        const int c4 = tid * 4;
        float4 k = *(const float4*)(g_qkv + (size_t)s0 * H3 + HID + h * HD + c4);
        const size_t ko = (size_t)h * 32 * 64 + (size_t)st * 64 + c4;
        *(uint32_t*)&g_kgh[ko]     = packh2(k.x, k.y);
        *(uint32_t*)&g_kgh[ko + 2] = packh2(k.z, k.w);
    }
    if (tid < 64) {
        const size_t go = (size_t)h * 64 * 32 + (size_t)tid * 32 + st;
        g_vtgh[go] = vth[tid][0];
    }
}

// ================= MMA attention core (plain fp16) =================
#define MASKV (-3.0e38f)
#define ATS   72
#define ATILE (64 * ATS)
#define AT_SMEM ((1 + 4) * ATILE * 2)   // Q + 2 stages x (K, Vt)

template<int NKT, int MODE>
__device__ __forceinline__ void attn_compute(
    uint32_t sKh, uint32_t sVh, int kb, int qr0,
    int t, int brow, int bcol,
    const uint32_t qh[4][4],
    float o[8][4], float& m0, float& m1, float& l0, float& l1)
{
    constexpr int NJ = NKT / 8;
    float sc[NJ][4];

    // ---- S = Q K^T ----
#pragma unroll
    for (int jp = 0; jp < NKT / 16; jp++) {
#pragma unroll
        for (int e = 0; e < 4; e++) { sc[2 * jp][e] = 0.f; sc[2 * jp + 1][e] = 0.f; }
#pragma unroll
        for (int c = 0; c < 4; c++) {
            uint32_t b0, b1, b2, b3;
            const uint32_t ka = sKh + (uint32_t)((jp * 16 + brow) * ATS + c * 16 + bcol) * 2;
            ldm_x4(b0, b1, b2, b3, ka);
            float* s0p = sc[2 * jp];
            float* s1p = sc[2 * jp + 1];
            mma16816h(s0p[0], s0p[1], s0p[2], s0p[3],
                      qh[c][0], qh[c][1], qh[c][2], qh[c][3], b0, b1);
            mma16816h(s1p[0], s1p[1], s1p[2], s1p[3],
                      qh[c][0], qh[c][1], qh[c][2], qh[c][3], b2, b3);
        }
    }

    // ---- mask + row max ----
    float tm0 = MASKV, tm1 = MASKV;
#pragma unroll
    for (int jn = 0; jn < NJ; jn++) {
#pragma unroll
        for (int e = 0; e < 2; e++) {
            if (MODE < 2) {
                const int ci  = jn * 8 + 2 * t + e;
                const int key = (MODE == 1) ? (ci * GSTRIDE) : (kb + ci);
                int d0 = qr0 - key; d0 = d0 < 0 ? -d0 : d0;
                int d1 = qr0 + 8 - key; d1 = d1 < 0 ? -d1 : d1;
                const bool in0 = (MODE == 1) ? (d0 > WIN) : (d0 <= WIN);
                const bool in1 = (MODE == 1) ? (d1 > WIN) : (d1 <= WIN);
                if (!in0) sc[jn][e]     = MASKV;
                if (!in1) sc[jn][2 + e] = MASKV;
            }
            tm0 = fmaxf(tm0, sc[jn][e]);
            tm1 = fmaxf(tm1, sc[jn][2 + e]);
        }
    }
    tm0 = fmaxf(tm0, __shfl_xor_sync(0xffffffffu, tm0, 1));
    tm0 = fmaxf(tm0, __shfl_xor_sync(0xffffffffu, tm0, 2));
    tm1 = fmaxf(tm1, __shfl_xor_sync(0xffffffffu, tm1, 1));
    tm1 = fmaxf(tm1, __shfl_xor_sync(0xffffffffu, tm1, 2));

    const float mn0 = fmaxf(m0, tm0), mn1 = fmaxf(m1, tm1);
    const float e0 = __expf(m0 - mn0), e1 = __expf(m1 - mn1);
    m0 = mn0; m1 = mn1; l0 *= e0; l1 *= e1;
#pragma unroll
    for (int nb = 0; nb < 8; nb++) {
        o[nb][0] *= e0; o[nb][1] *= e0; o[nb][2] *= e1; o[nb][3] *= e1;
    }

    // ---- P = exp(S - m) (plain fp16); O += P V ----
    float s0 = 0.f, s1 = 0.f;
#pragma unroll
    for (int c = 0; c < NKT / 16; c++) {
        const float p00 = __expf(sc[2 * c][0] - m0);
        const float p01 = __expf(sc[2 * c][1] - m0);
        const float p02 = __expf(sc[2 * c][2] - m1);
        const float p03 = __expf(sc[2 * c][3] - m1);
        const float p10 = __expf(sc[2 * c + 1][0] - m0);
        const float p11 = __expf(sc[2 * c + 1][1] - m0);
        const float p12 = __expf(sc[2 * c + 1][2] - m1);
        const float p13 = __expf(sc[2 * c + 1][3] - m1);
        s0 += (p00 + p01) + (p10 + p11);
        s1 += (p02 + p03) + (p12 + p13);
        uint32_t ah[4];
        ah[0] = packh2(p00, p01);
        ah[1] = packh2(p02, p03);
        ah[2] = packh2(p10, p11);
        ah[3] = packh2(p12, p13);
#pragma unroll
        for (int np = 0; np < 4; np++) {
            uint32_t v0, v1, v2, v3;
            const uint32_t va = sVh + (uint32_t)((np * 16 + brow) * ATS + c * 16 + bcol) * 2;
            ldm_x4(v0, v1, v2, v3, va);
            float* oa = o[2 * np];
            float* ob = o[2 * np + 1];
            mma16816h(oa[0], oa[1], oa[2], oa[3], ah[0], ah[1], ah[2], ah[3], v0, v1);
            mma16816h(ob[0], ob[1], ob[2], ob[3], ah[0], ah[1], ah[2], ah[3], v2, v3);
        }
    }
    s0 += __shfl_xor_sync(0xffffffffu, s0, 1);
    s0 += __shfl_xor_sync(0xffffffffu, s0, 2);
    s1 += __shfl_xor_sync(0xffffffffu, s1, 1);
    s1 += __shfl_xor_sync(0xffffffffu, s1, 2);
    l0 += s0; l1 += s1;
}

// ================= band + global-col attention =================
__global__ __launch_bounds__(128) void attn_mma() {
    extern __shared__ __half sm_[];
    const uint32_t sb = smem_u32(sm_);
    const uint32_t sQ = sb;

    const int qt = blockIdx.x, h = blockIdx.y, q0 = qt * 64;
    const int tid = threadIdx.x, wid = tid >> 5, lane = tid & 31;
    const int g = lane >> 2, t = lane & 3;
    const int brow = ((lane >> 4) << 3) + (lane & 7);
    const int bcol = ((lane >> 3) & 1) * 8;

    {
        const __half* qp = g_qh + (size_t)h * SEQ * 64 + (size_t)q0 * 64;
        for (int idx = tid; idx < 512; idx += 128) {
            const int r = idx >> 3, c = idx & 7;
            cp16(sQ + (uint32_t)(r * ATS + c * 8) * 2, qp + r * 64 + c * 8);
        }
    }
    CP_COMMIT();

    const int kb0 = q0 >= WIN ? q0 - WIN : 0;
    const int kb1 = (q0 + 64 + WIN) <= SEQ ? (q0 + 64 + WIN) : SEQ;
    const int nband = (kb1 - kb0) >> 6;
    const int T = nband + 1;

    auto stage_base = [&](int s) { return sb + (uint32_t)(1 + 2 * s) * ATILE * 2; };
    auto stage_band = [&](int s, int kb) {
        const uint32_t b = stage_base(s);
        const __half* khp = g_kh + (size_t)h * SEQ * 64 + (size_t)kb * 64;
        const __half* vhp = g_vth + (size_t)h * 64 * SEQ + kb;
        for (int idx = tid; idx < 512; idx += 128) {
            const int r = idx >> 3, c = idx & 7;
            const uint32_t so = (uint32_t)(r * ATS + c * 8) * 2;
            cp16(b + so,             khp + r * 64 + c * 8);
            cp16(b + ATILE * 2 + so, vhp + (size_t)r * SEQ + c * 8);
        }
    };
    auto stage_glob = [&](int s) {
        const uint32_t b = stage_base(s);
        const __half* khp = g_kgh + (size_t)h * 32 * 64;
        const __half* vhp = g_vtgh + (size_t)h * 64 * 32;
        for (int idx = tid; idx < 256; idx += 128) {
            const int r = idx >> 3, c = idx & 7;
            cp16(b + (uint32_t)(r * ATS + c * 8) * 2, khp + r * 64 + c * 8);
        }
        for (int idx = tid; idx < 256; idx += 128) {
            const int r = idx >> 2, c = idx & 3;
            cp16(b + ATILE * 2 + (uint32_t)(r * ATS + c * 8) * 2, vhp + r * 32 + c * 8);
        }
    };

    stage_band(0, kb0);
    CP_COMMIT();
    CP_WAIT1();
    __syncthreads();

    uint32_t qh[4][4];
    {
        const int ar = wid * 16 + ((lane >> 3) & 1) * 8 + (lane & 7);
        const int ac = (lane >> 4) * 8;
#pragma unroll
        for (int c = 0; c < 4; c++) {
            const uint32_t ad = sQ + (uint32_t)(ar * ATS + c * 16 + ac) * 2;
            ldm_x4(qh[c][0], qh[c][1], qh[c][2], qh[c][3], ad);
        }
    }

    float o[8][4];
#pragma unroll
    for (int nb = 0; nb < 8; nb++)
#pragma unroll
        for (int c = 0; c < 4; c++) o[nb][c] = 0.f;
    float m0 = -1e30f, m1 = -1e30f, l0 = 0.f, l1 = 0.f;
    const int qr0 = q0 + wid * 16 + g;

    for (int i = 0; i < T; i++) {
        if (i + 1 < T) {
            if (i + 1 < nband) stage_band((i + 1) & 1, kb0 + (i + 1) * 64);
            else stage_glob((i + 1) & 1);
            CP_COMMIT();
            CP_WAIT1();
        } else {
            CP_WAIT0();
        }
        __syncthreads();
        const uint32_t b = stage_base(i & 1);
        if (i < nband)
            attn_compute<64, 0>(b, b + ATILE * 2, kb0 + i * 64, qr0,
                                t, brow, bcol, qh, o, m0, m1, l0, l1);
        else
            attn_compute<32, 1>(b, b + ATILE * 2, 0, qr0,
                                t, brow, bcol, qh, o, m0, m1, l0, l1);
        __syncthreads();
    }

    const float i0 = 1.f / l0, i1 = 1.f / l1;
    const int row0 = q0 + wid * 16 + g;
#pragma unroll
    for (int nb = 0; nb < 8; nb++) {
        const size_t ofs0 = (size_t)row0 * HID + h * HD + nb * 8 + 2 * t;
        const size_t ofs1 = ofs0 + (size_t)8 * HID;
        *(uint32_t*)&g_ah[ofs0] = packh2(o[nb][0] * i0, o[nb][1] * i0);
        *(uint32_t*)&g_ah[ofs1] = packh2(o[nb][2] * i1, o[nb][3] * i1);
    }
}

// ================= global rows: MMA over all 2048 keys =================
#define GA_QSZ   (32 * ATS * 2)
#define GA_TILES (2 * 2 * 2 * ATILE * 2)   // 2 stages x 2 kp x (K, Vt)
#define GA_OBUF  (2 * 16 * 64 * 4)
#define GA_SMEM  (GA_QSZ + GA_TILES + GA_OBUF + 256)

__global__ __launch_bounds__(128) void attn_global_mma() {
    extern __shared__ __half smg2[];
    const uint32_t sb = smem_u32(smg2);
    const int h = blockIdx.x;
    const int tid = threadIdx.x, wid = tid >> 5, lane = tid & 31;
    const int g = lane >> 2, t = lane & 3;
    const int rh = wid & 1, kp = wid >> 1;
    const int brow = ((lane >> 4) << 3) + (lane & 7);
    const int bcol = ((lane >> 3) & 1) * 8;

    const uint32_t sQ = sb;
    const uint32_t tiles0 = sb + GA_QSZ;
    float* obuf = (float*)(smg2 + (32 * ATS + 8 * ATILE));
    float* slm  = obuf + 2 * 16 * 64;
    float* sll  = slm + 32;

    {
        const __half* qp = g_qh + (size_t)h * SEQ * 64;
        for (int idx = tid; idx < 256; idx += 128) {
            const int r = idx >> 3, c = idx & 7;
            cp16(sQ + (uint32_t)(r * ATS + c * 8) * 2, qp + (size_t)r * 64 * 64 + c * 8);
        }
    }
    CP_COMMIT();

    auto stage_tiles = [&](int st, int it) {
#pragma unroll
        for (int kpi = 0; kpi < 2; kpi++) {
            const int kt = (it * 2 + kpi) * 64;
            const uint32_t b = tiles0 + (uint32_t)((st * 2 + kpi) * 2) * ATILE * 2;
            const __half* khp = g_kh + (size_t)h * SEQ * 64 + (size_t)kt * 64;
            const __half* vhp = g_vth + (size_t)h * 64 * SEQ + kt;
            for (int idx = tid; idx < 512; idx += 128) {
                const int r = idx >> 3, c = idx & 7;
                const uint32_t so = (uint32_t)(r * ATS + c * 8) * 2;
                cp16(b + so,             khp + r * 64 + c * 8);
                cp16(b + ATILE * 2 + so, vhp + (size_t)r * SEQ + c * 8);
            }
        }
    };

    stage_tiles(0, 0);
    CP_COMMIT();
    CP_WAIT1();
    __syncthreads();

    uint32_t qh[4][4];
    {
        const int ar = rh * 16 + ((lane >> 3) & 1) * 8 + (lane & 7);
        const int ac = (lane >> 4) * 8;
#pragma unroll
        for (int c = 0; c < 4; c++) {
            const uint32_t ad = sQ + (uint32_t)(ar * ATS + c * 16 + ac) * 2;
            ldm_x4(qh[c][0], qh[c][1], qh[c][2], qh[c][3], ad);
        }
    }

    float o[8][4];
#pragma unroll
    for (int nb = 0; nb < 8; nb++)
#pragma unroll
        for (int c = 0; c < 4; c++) o[nb][c] = 0.f;
    float m0 = -1e30f, m1 = -1e30f, l0 = 0.f, l1 = 0.f;

    for (int it = 0; it < 16; it++) {
        if (it + 1 < 16) {
            stage_tiles((it + 1) & 1, it + 1);
            CP_COMMIT();
            CP_WAIT1();
        } else {
            CP_WAIT0();
        }
        __syncthreads();
        const uint32_t b = tiles0 + (uint32_t)(((it & 1) * 2 + kp) * 2) * ATILE * 2;
        attn_compute<64, 2>(b, b + ATILE * 2, 0, 0,
                            t, brow, bcol, qh, o, m0, m1, l0, l1);
        __syncthreads();
    }

    __syncthreads();
    if (kp == 1) {
        float* ob = obuf + rh * 16 * 64;
#pragma unroll
        for (int nb = 0; nb < 8; nb++) {
            ob[g * 64 + nb * 8 + 2 * t]           = o[nb][0];
            ob[g * 64 + nb * 8 + 2 * t + 1]       = o[nb][1];
            ob[(g + 8) * 64 + nb * 8 + 2 * t]     = o[nb][2];
            ob[(g + 8) * 64 + nb * 8 + 2 * t + 1] = o[nb][3];
        }
        if (t == 0) {
            slm[rh * 16 + g] = m0; slm[rh * 16 + g + 8] = m1;
            sll[rh * 16 + g] = l0; sll[rh * 16 + g + 8] = l1;
        }
    }
    __syncthreads();
    if (kp == 0) {
        const float pm0 = slm[rh * 16 + g], pm1 = slm[rh * 16 + g + 8];
        const float pl0 = sll[rh * 16 + g], pl1 = sll[rh * 16 + g + 8];
        const float M0 = fmaxf(m0, pm0), M1 = fmaxf(m1, pm1);
        const float e0 = __expf(m0 - M0), f0 = __expf(pm0 - M0);
        const float e1 = __expf(m1 - M1), f1 = __expf(pm1 - M1);
        const float L0 = l0 * e0 + pl0 * f0;
        const float L1 = l1 * e1 + pl1 * f1;
        const float i0 = 1.f / L0, i1 = 1.f / L1;
        float* ob = obuf + rh * 16 * 64;
        const int qi0 = (rh * 16 + g) * 64;
        const int qi1 = (rh * 16 + g + 8) * 64;
#pragma unroll
        for (int nb = 0; nb < 8; nb++) {
            const int cc = nb * 8 + 2 * t;
            const float r00 = (o[nb][0] * e0 + ob[g * 64 + cc] * f0) * i0;
            const float r01 = (o[nb][1] * e0 + ob[g * 64 + cc + 1] * f0) * i0;
            const float r10 = (o[nb][2] * e1 + ob[(g + 8) * 64 + cc] * f1) * i1;
            const float r11 = (o[nb][3] * e1 + ob[(g + 8) * 64 + cc + 1] * f1) * i1;
            const size_t ofs0 = (size_t)qi0 * HID + h * HD + cc;
            const size_t ofs1 = (size_t)qi1 * HID + h * HD + cc;
            *(uint32_t*)&g_ah[ofs0] = packh2(r00, r01);
            *(uint32_t*)&g_ah[ofs1] = packh2(r10, r11);
        }
    }
}

// ---------------- launch: forked-stream DAG (lazy-init handles) ----------------
static cudaStream_t g_s1 = nullptr, g_s2 = nullptr;
static cudaEvent_t  g_eFork, g_eX, g_eWo, g_ePrep, g_eG;

extern "C" void kernel_launch(void* const* d_in, const int* in_sizes, int n_in,
                              void* d_out, int out_size) {
    const float* x    = (const float*)d_in[0];
    const float* Wqkv = (const float*)d_in[1];
    const float* Wout = (const float*)d_in[2];
    float* out = (float*)d_out;

    float* qkv = nullptr;
    cudaGetSymbolAddress((void**)&qkv, g_qkv);
    __half *xh, *wqh, *woh, *wol, *ah;
    cudaGetSymbolAddress((void**)&xh,  g_xh);
    cudaGetSymbolAddress((void**)&wqh, g_wqh);
    cudaGetSymbolAddress((void**)&woh, g_woh); cudaGetSymbolAddress((void**)&wol, g_wol);
    cudaGetSymbolAddress((void**)&ah,  g_ah);

    if (g_s1 == nullptr) {
        cudaStreamCreateWithFlags(&g_s1, cudaStreamNonBlocking);
        cudaStreamCreateWithFlags(&g_s2, cudaStreamNonBlocking);
        cudaEventCreateWithFlags(&g_eFork, cudaEventDisableTiming);
        cudaEventCreateWithFlags(&g_eX,    cudaEventDisableTiming);
        cudaEventCreateWithFlags(&g_eWo,   cudaEventDisableTiming);
        cudaEventCreateWithFlags(&g_ePrep, cudaEventDisableTiming);
        cudaEventCreateWithFlags(&g_eG,    cudaEventDisableTiming);
        cudaFuncSetAttribute(gemm_f16p,    cudaFuncAttributeMaxDynamicSharedMemorySize, GFP_SMEM);
        cudaFuncSetAttribute(gemm_f16<64>, cudaFuncAttributeMaxDynamicSharedMemorySize, GF_SMEM64);
        cudaFuncSetAttribute(attn_mma, cudaFuncAttributeMaxDynamicSharedMemorySize, AT_SMEM);
        cudaFuncSetAttribute(attn_global_mma, cudaFuncAttributeMaxDynamicSharedMemorySize, GA_SMEM);
    }

    // fork s1 off the (capture) default stream
    cudaEventRecord(g_eFork, 0);
    cudaStreamWaitEvent(g_s1, g_eFork, 0);

    // s1: x -> fp16, then Wout split (only needed by final GEMM)
    conv_half<<<(SEQ * HID / 4 + 255) / 256, 256, 0, g_s1>>>(x, xh, SEQ * HID / 4);
    cudaEventRecord(g_eX, g_s1);
    split_half<<<(HID * HID / 4 + 255) / 256, 256, 0, g_s1>>>(Wout, woh, wol, HID * HID / 4);
    cudaEventRecord(g_eWo, g_s1);

    // default: Wqkv -> plain fp16, then QKV GEMM
    conv_half<<<(H3 * HID / 4 + 255) / 256, 256>>>(Wqkv, wqh, H3 * HID / 4);
    cudaStreamWaitEvent(0, g_eX, 0);
    gemm_f16p<<<dim3(H3 / 128, SEQ / 128), 256, GFP_SMEM>>>(xh, wqh, qkv, SEQ, H3, HID);

    // default: per-head fp16 operands
    prep_attn<<<dim3(SEQ / 64, NHEAD), 256>>>();
    cudaEventRecord(g_ePrep, 0);

    // s2: global-row attention in parallel with banded attention
    cudaStreamWaitEvent(g_s2, g_ePrep, 0);
    attn_global_mma<<<NHEAD, 128, GA_SMEM, g_s2>>>();
    cudaEventRecord(g_eG, g_s2);

    // default: banded attention
    attn_mma<<<dim3(SEQ / 64, NHEAD), 128, AT_SMEM>>>();

    // join everything, then out-projection (2-term)
    cudaStreamWaitEvent(0, g_eG, 0);
    cudaStreamWaitEvent(0, g_eWo, 0);
    gemm_f16<64><<<dim3(HID / 128, SEQ / 64), 256, GF_SMEM64>>>(ah, woh, wol, out, SEQ, HID, HID);
}

// round 17
// speedup vs baseline: 1.9093x; 1.2767x over previous
#include <cuda_runtime.h>
#include <cuda_fp16.h>
#include <cstdint>

// ---------------- problem constants ----------------
#define SEQ   2048
#define HID   1024
#define H3    3072
#define NHEAD 16
#define HD    64
#define WIN   128
#define GSTRIDE 64

// ---------------- mma / ldmatrix / cp.async helpers ----------------
__device__ __forceinline__ void mma16816h(float& c0, float& c1, float& c2, float& c3,
                                          uint32_t a0, uint32_t a1, uint32_t a2, uint32_t a3,
                                          uint32_t b0, uint32_t b1) {
    asm volatile(
        "mma.sync.aligned.m16n8k16.row.col.f32.f16.f16.f32 "
        "{%0,%1,%2,%3}, {%4,%5,%6,%7}, {%8,%9}, {%0,%1,%2,%3};"
        : "+f"(c0), "+f"(c1), "+f"(c2), "+f"(c3)
        : "r"(a0), "r"(a1), "r"(a2), "r"(a3), "r"(b0), "r"(b1));
}
__device__ __forceinline__ void ldm_x4(uint32_t& r0, uint32_t& r1, uint32_t& r2, uint32_t& r3,
                                       uint32_t addr) {
    asm volatile("ldmatrix.sync.aligned.m8n8.x4.shared.b16 {%0,%1,%2,%3}, [%4];"
                 : "=r"(r0), "=r"(r1), "=r"(r2), "=r"(r3) : "r"(addr));
}
__device__ __forceinline__ uint32_t smem_u32(const void* p) {
    uint32_t a;
    asm("{ .reg .u64 t; cvta.to.shared.u64 t, %1; cvt.u32.u64 %0, t; }" : "=r"(a) : "l"(p));
    return a;
}
__device__ __forceinline__ void cp16(uint32_t saddr, const void* gptr) {
    asm volatile("cp.async.cg.shared.global [%0], [%1], 16;" :: "r"(saddr), "l"(gptr));
}
#define CP_COMMIT() asm volatile("cp.async.commit_group;" ::: "memory")
#define CP_WAIT1()  asm volatile("cp.async.wait_group 1;" ::: "memory")
#define CP_WAIT0()  asm volatile("cp.async.wait_group 0;" ::: "memory")

// fp16 helpers
__device__ __forceinline__ uint32_t packh2(float a, float b) {
    __half2 h = __floats2half2_rn(a, b);
    uint32_t r; *(__half2*)&r = h; return r;
}

// ---------------- scratch (device globals) ----------------
__device__ float g_qkv[SEQ * H3];
__device__ __align__(16) __half g_xh[SEQ * HID];
__device__ __align__(16) __half g_wqh[H3 * HID];
__device__ __align__(16) __half g_woh[HID * HID];
__device__ __align__(16) __half g_ah[SEQ * HID];
__device__ __align__(16) __half g_qh[NHEAD * SEQ * 64];
__device__ __align__(16) __half g_kh[NHEAD * SEQ * 64];
__device__ __align__(16) __half g_vth[NHEAD * 64 * SEQ];
__device__ __align__(16) __half g_kgh[NHEAD * 32 * 64];
__device__ __align__(16) __half g_vtgh[NHEAD * 64 * 32];

// ---------------- conversions ----------------
__global__ __launch_bounds__(256) void conv_half(const float* __restrict__ in,
                                                 __half* __restrict__ out, int n4) {
    int i = blockIdx.x * blockDim.x + threadIdx.x;
    if (i >= n4) return;
    float4 v = ((const float4*)in)[i];
    uint32_t* op = (uint32_t*)out;
    op[2 * i]     = packh2(v.x, v.y);
    op[2 * i + 1] = packh2(v.z, v.w);
}

// ---------------- plain fp16 GEMM: C = A @ B^T, templated tiles ----------------
// BM rows x 128 cols CTA tile, BK-deep chunks, 8 warps ((BM/32)M x 4N groups of 32).
template<int BM, int BK>
__global__ __launch_bounds__(256) void gemm_f16p(const __half* __restrict__ Ag,
                                                 const __half* __restrict__ Bg,
                                                 float* __restrict__ C,
                                                 int M, int N, int K) {
    constexpr int ST   = BK + 8;        // smem row stride (conflict-free: 9r mod 8 = r mod 8)
    constexpr int ABUF = BM * ST;
    constexpr int BBUF = 128 * ST;
    constexpr int STGE = ABUF + BBUF;
    constexpr int IM   = BM / 32;
    constexpr int C8   = BK / 8;        // 16B chunks per row

    extern __shared__ __half smf[];
    const uint32_t sbase = smem_u32(smf);

    const int tid = threadIdx.x;
    const int wid = tid >> 5;
    const int lane = tid & 31;
    const int g = lane >> 2;
    const int t = lane & 3;
    const int warp_m = (wid & 1) * (BM / 2);
    const int warp_n = (wid >> 1) * 32;
    const int tile_m = blockIdx.y * BM;
    const int tile_n = blockIdx.x * 128;

    const int a_row = warp_m + ((lane >> 3) & 1) * 8 + (lane & 7);
    const int a_col = (lane >> 4) * 8;
    const int b_row = warp_n + (lane >> 4) * 8 + (lane & 7);
    const int b_col = ((lane >> 3) & 1) * 8;

    float acc[IM][4][4];
#pragma unroll
    for (int im = 0; im < IM; im++)
#pragma unroll
        for (int jn = 0; jn < 4; jn++)
#pragma unroll
            for (int c = 0; c < 4; c++) acc[im][jn][c] = 0.f;

    auto load_stage = [&](int st, int k0) {
        const uint32_t sb = sbase + (uint32_t)st * STGE * 2;
        for (int idx = tid; idx < BM * C8; idx += 256) {
            const int row = idx / C8;
            const int c8  = (idx % C8) * 8;
            cp16(sb + (uint32_t)(row * ST + c8) * 2,
                 Ag + (size_t)(tile_m + row) * K + k0 + c8);
        }
        for (int idx = tid; idx < 128 * C8; idx += 256) {
            const int row = idx / C8;
            const int c8  = (idx % C8) * 8;
            cp16(sb + ABUF * 2 + (uint32_t)(row * ST + c8) * 2,
                 Bg + (size_t)(tile_n + row) * K + k0 + c8);
        }
    };

    const int nchunks = K / BK;
    load_stage(0, 0);
    CP_COMMIT();

    for (int ch = 0; ch < nchunks; ch++) {
        if (ch + 1 < nchunks) load_stage((ch + 1) & 1, (ch + 1) * BK);
        CP_COMMIT();
        CP_WAIT1();
        __syncthreads();

        const uint32_t sb = sbase + (uint32_t)(ch & 1) * STGE * 2;
#pragma unroll
        for (int ks = 0; ks < BK; ks += 16) {
            uint32_t aH[IM][4];
#pragma unroll
            for (int im = 0; im < IM; im++) {
                const uint32_t ad = sb + (uint32_t)((a_row + im * 16) * ST + ks + a_col) * 2;
                ldm_x4(aH[im][0], aH[im][1], aH[im][2], aH[im][3], ad);
            }
#pragma unroll
            for (int jp = 0; jp < 2; jp++) {
                uint32_t bh0, bh1, bh2, bh3;
                const uint32_t bd = sb + ABUF * 2
                                  + (uint32_t)((b_row + jp * 16) * ST + ks + b_col) * 2;
                ldm_x4(bh0, bh1, bh2, bh3, bd);
#pragma unroll
                for (int im = 0; im < IM; im++) {
                    float* a0p = acc[im][2 * jp];
                    float* a1p = acc[im][2 * jp + 1];
                    mma16816h(a0p[0], a0p[1], a0p[2], a0p[3],
                              aH[im][0], aH[im][1], aH[im][2], aH[im][3], bh0, bh1);
                    mma16816h(a1p[0], a1p[1], a1p[2], a1p[3],
                              aH[im][0], aH[im][1], aH[im][2], aH[im][3], bh2, bh3);
                }
            }
        }
        __syncthreads();
    }

#pragma unroll
    for (int im = 0; im < IM; im++) {
        const int row = tile_m + warp_m + im * 16 + g;
#pragma unroll
        for (int jn = 0; jn < 4; jn++) {
            const int col = tile_n + warp_n + jn * 8 + 2 * t;
            float2 v0; v0.x = acc[im][jn][0]; v0.y = acc[im][jn][1];
            float2 v1; v1.x = acc[im][jn][2]; v1.y = acc[im][jn][3];
            *(float2*)(C + (size_t)row * N + col)       = v0;
            *(float2*)(C + (size_t)(row + 8) * N + col) = v1;
        }
    }
}
#define GFP64_SMEM (2 * ((64 + 128) * (64 + 8)) * 2)

// ---------------- prep: per-head plain fp16 Q (scaled), K, Vt ----------------
#define PVS 66
__global__ __launch_bounds__(256) void prep_attn() {
    const int st = blockIdx.x;
    const int h  = blockIdx.y;
    const int s0 = st * 64;
    const int tid = threadIdx.x;

    __shared__ __half vth[64][PVS];

    for (int idx = tid; idx < 1024; idx += 256) {
        const int r = idx >> 4, c4 = (idx & 15) << 2;
        const size_t base = (size_t)(s0 + r) * H3 + h * HD + c4;
        const size_t qo = (size_t)h * SEQ * 64 + (size_t)(s0 + r) * 64 + c4;
        float4 q = *(const float4*)(g_qkv + base);
        *(uint32_t*)&g_qh[qo]     = packh2(q.x * 0.125f, q.y * 0.125f);
        *(uint32_t*)&g_qh[qo + 2] = packh2(q.z * 0.125f, q.w * 0.125f);
        float4 k = *(const float4*)(g_qkv + base + HID);
        *(uint32_t*)&g_kh[qo]     = packh2(k.x, k.y);
        *(uint32_t*)&g_kh[qo + 2] = packh2(k.z, k.w);
        float4 v = *(const float4*)(g_qkv + base + 2 * HID);
        vth[c4 + 0][r] = __float2half_rn(v.x);
        vth[c4 + 1][r] = __float2half_rn(v.y);
        vth[c4 + 2][r] = __float2half_rn(v.z);
        vth[c4 + 3][r] = __float2half_rn(v.w);
    }
    __syncthreads();

    for (int idx = tid; idx < 2048; idx += 256) {
        const int d = idx >> 5, cp = (idx & 31) << 1;
        const size_t vo = (size_t)h * 64 * SEQ + (size_t)d * SEQ + s0 + cp;
        *(uint32_t*)&g_vth[vo] = *(const uint32_t*)&vth[d][cp];
    }
    if (tid < 16) {
        const int c4 = tid * 4;
        float4 k = *(const float4*)(g_qkv + (size_t)s0 * H3 + HID + h * HD + c4);
        const size_t ko = (size_t)h * 32 * 64 + (size_t)st * 64 + c4;
        *(uint32_t*)&g_kgh[ko]     = packh2(k.x, k.y);
        *(uint32_t*)&g_kgh[ko + 2] = packh2(k.z, k.w);
    }
    if (tid < 64) {
        const size_t go = (size_t)h * 64 * 32 + (size_t)tid * 32 + st;
        g_vtgh[go] = vth[tid][0];
    }
}

// ================= MMA attention core (plain fp16) =================
#define MASKV (-3.0e38f)
#define ATS   72
#define ATILE (64 * ATS)
#define AT_SMEM ((1 + 4) * ATILE * 2)

template<int NKT, int MODE>
__device__ __forceinline__ void attn_compute(
    uint32_t sKh, uint32_t sVh, int kb, int qr0,
    int t, int brow, int bcol,
    const uint32_t qh[4][4],
    float o[8][4], float& m0, float& m1, float& l0, float& l1)
{
    constexpr int NJ = NKT / 8;
    float sc[NJ][4];

#pragma unroll
    for (int jp = 0; jp < NKT / 16; jp++) {
#pragma unroll
        for (int e = 0; e < 4; e++) { sc[2 * jp][e] = 0.f; sc[2 * jp + 1][e] = 0.f; }
#pragma unroll
        for (int c = 0; c < 4; c++) {
            uint32_t b0, b1, b2, b3;
            const uint32_t ka = sKh + (uint32_t)((jp * 16 + brow) * ATS + c * 16 + bcol) * 2;
            ldm_x4(b0, b1, b2, b3, ka);
            float* s0p = sc[2 * jp];
            float* s1p = sc[2 * jp + 1];
            mma16816h(s0p[0], s0p[1], s0p[2], s0p[3],
                      qh[c][0], qh[c][1], qh[c][2], qh[c][3], b0, b1);
            mma16816h(s1p[0], s1p[1], s1p[2], s1p[3],
                      qh[c][0], qh[c][1], qh[c][2], qh[c][3], b2, b3);
        }
    }

    float tm0 = MASKV, tm1 = MASKV;
#pragma unroll
    for (int jn = 0; jn < NJ; jn++) {
#pragma unroll
        for (int e = 0; e < 2; e++) {
            if (MODE < 2) {
                const int ci  = jn * 8 + 2 * t + e;
                const int key = (MODE == 1) ? (ci * GSTRIDE) : (kb + ci);
                int d0 = qr0 - key; d0 = d0 < 0 ? -d0 : d0;
                int d1 = qr0 + 8 - key; d1 = d1 < 0 ? -d1 : d1;
                const bool in0 = (MODE == 1) ? (d0 > WIN) : (d0 <= WIN);
                const bool in1 = (MODE == 1) ? (d1 > WIN) : (d1 <= WIN);
                if (!in0) sc[jn][e]     = MASKV;
                if (!in1) sc[jn][2 + e] = MASKV;
            }
            tm0 = fmaxf(tm0, sc[jn][e]);
            tm1 = fmaxf(tm1, sc[jn][2 + e]);
        }
    }
    tm0 = fmaxf(tm0, __shfl_xor_sync(0xffffffffu, tm0, 1));
    tm0 = fmaxf(tm0, __shfl_xor_sync(0xffffffffu, tm0, 2));
    tm1 = fmaxf(tm1, __shfl_xor_sync(0xffffffffu, tm1, 1));
    tm1 = fmaxf(tm1, __shfl_xor_sync(0xffffffffu, tm1, 2));

    const float mn0 = fmaxf(m0, tm0), mn1 = fmaxf(m1, tm1);
    const float e0 = __expf(m0 - mn0), e1 = __expf(m1 - mn1);
    m0 = mn0; m1 = mn1; l0 *= e0; l1 *= e1;
#pragma unroll
    for (int nb = 0; nb < 8; nb++) {
        o[nb][0] *= e0; o[nb][1] *= e0; o[nb][2] *= e1; o[nb][3] *= e1;
    }

    float s0 = 0.f, s1 = 0.f;
#pragma unroll
    for (int c = 0; c < NKT / 16; c++) {
        const float p00 = __expf(sc[2 * c][0] - m0);
        const float p01 = __expf(sc[2 * c][1] - m0);
        const float p02 = __expf(sc[2 * c][2] - m1);
        const float p03 = __expf(sc[2 * c][3] - m1);
        const float p10 = __expf(sc[2 * c + 1][0] - m0);
        const float p11 = __expf(sc[2 * c + 1][1] - m0);
        const float p12 = __expf(sc[2 * c + 1][2] - m1);
        const float p13 = __expf(sc[2 * c + 1][3] - m1);
        s0 += (p00 + p01) + (p10 + p11);
        s1 += (p02 + p03) + (p12 + p13);
        uint32_t ah[4];
        ah[0] = packh2(p00, p01);
        ah[1] = packh2(p02, p03);
        ah[2] = packh2(p10, p11);
        ah[3] = packh2(p12, p13);
#pragma unroll
        for (int np = 0; np < 4; np++) {
            uint32_t v0, v1, v2, v3;
            const uint32_t va = sVh + (uint32_t)((np * 16 + brow) * ATS + c * 16 + bcol) * 2;
            ldm_x4(v0, v1, v2, v3, va);
            float* oa = o[2 * np];
            float* ob = o[2 * np + 1];
            mma16816h(oa[0], oa[1], oa[2], oa[3], ah[0], ah[1], ah[2], ah[3], v0, v1);
            mma16816h(ob[0], ob[1], ob[2], ob[3], ah[0], ah[1], ah[2], ah[3], v2, v3);
        }
    }
    s0 += __shfl_xor_sync(0xffffffffu, s0, 1);
    s0 += __shfl_xor_sync(0xffffffffu, s0, 2);
    s1 += __shfl_xor_sync(0xffffffffu, s1, 1);
    s1 += __shfl_xor_sync(0xffffffffu, s1, 2);
    l0 += s0; l1 += s1;
}

// ================= band + global-col attention =================
__global__ __launch_bounds__(128) void attn_mma() {
    extern __shared__ __half sm_[];
    const uint32_t sb = smem_u32(sm_);
    const uint32_t sQ = sb;

    const int qt = blockIdx.x, h = blockIdx.y, q0 = qt * 64;
    const int tid = threadIdx.x, wid = tid >> 5, lane = tid & 31;
    const int g = lane >> 2, t = lane & 3;
    const int brow = ((lane >> 4) << 3) + (lane & 7);
    const int bcol = ((lane >> 3) & 1) * 8;

    {
        const __half* qp = g_qh + (size_t)h * SEQ * 64 + (size_t)q0 * 64;
        for (int idx = tid; idx < 512; idx += 128) {
            const int r = idx >> 3, c = idx & 7;
            cp16(sQ + (uint32_t)(r * ATS + c * 8) * 2, qp + r * 64 + c * 8);
        }
    }
    CP_COMMIT();

    const int kb0 = q0 >= WIN ? q0 - WIN : 0;
    const int kb1 = (q0 + 64 + WIN) <= SEQ ? (q0 + 64 + WIN) : SEQ;
    const int nband = (kb1 - kb0) >> 6;
    const int T = nband + 1;

    auto stage_base = [&](int s) { return sb + (uint32_t)(1 + 2 * s) * ATILE * 2; };
    auto stage_band = [&](int s, int kb) {
        const uint32_t b = stage_base(s);
        const __half* khp = g_kh + (size_t)h * SEQ * 64 + (size_t)kb * 64;
        const __half* vhp = g_vth + (size_t)h * 64 * SEQ + kb;
        for (int idx = tid; idx < 512; idx += 128) {
            const int r = idx >> 3, c = idx & 7;
            const uint32_t so = (uint32_t)(r * ATS + c * 8) * 2;
            cp16(b + so,             khp + r * 64 + c * 8);
            cp16(b + ATILE * 2 + so, vhp + (size_t)r * SEQ + c * 8);
        }
    };
    auto stage_glob = [&](int s) {
        const uint32_t b = stage_base(s);
        const __half* khp = g_kgh + (size_t)h * 32 * 64;
        const __half* vhp = g_vtgh + (size_t)h * 64 * 32;
        for (int idx = tid; idx < 256; idx += 128) {
            const int r = idx >> 3, c = idx & 7;
            cp16(b + (uint32_t)(r * ATS + c * 8) * 2, khp + r * 64 + c * 8);
        }
        for (int idx = tid; idx < 256; idx += 128) {
            const int r = idx >> 2, c = idx & 3;
            cp16(b + ATILE * 2 + (uint32_t)(r * ATS + c * 8) * 2, vhp + r * 32 + c * 8);
        }
    };

    stage_band(0, kb0);
    CP_COMMIT();
    CP_WAIT1();
    __syncthreads();

    uint32_t qh[4][4];
    {
        const int ar = wid * 16 + ((lane >> 3) & 1) * 8 + (lane & 7);
        const int ac = (lane >> 4) * 8;
#pragma unroll
        for (int c = 0; c < 4; c++) {
            const uint32_t ad = sQ + (uint32_t)(ar * ATS + c * 16 + ac) * 2;
            ldm_x4(qh[c][0], qh[c][1], qh[c][2], qh[c][3], ad);
        }
    }

    float o[8][4];
#pragma unroll
    for (int nb = 0; nb < 8; nb++)
#pragma unroll
        for (int c = 0; c < 4; c++) o[nb][c] = 0.f;
    float m0 = -1e30f, m1 = -1e30f, l0 = 0.f, l1 = 0.f;
    const int qr0 = q0 + wid * 16 + g;

    for (int i = 0; i < T; i++) {
        if (i + 1 < T) {
            if (i + 1 < nband) stage_band((i + 1) & 1, kb0 + (i + 1) * 64);
            else stage_glob((i + 1) & 1);
            CP_COMMIT();
            CP_WAIT1();
        } else {
            CP_WAIT0();
        }
        __syncthreads();
        const uint32_t b = stage_base(i & 1);
        if (i < nband)
            attn_compute<64, 0>(b, b + ATILE * 2, kb0 + i * 64, qr0,
                                t, brow, bcol, qh, o, m0, m1, l0, l1);
        else
            attn_compute<32, 1>(b, b + ATILE * 2, 0, qr0,
                                t, brow, bcol, qh, o, m0, m1, l0, l1);
        __syncthreads();
    }

    const float i0 = 1.f / l0, i1 = 1.f / l1;
    const int row0 = q0 + wid * 16 + g;
#pragma unroll
    for (int nb = 0; nb < 8; nb++) {
        const size_t ofs0 = (size_t)row0 * HID + h * HD + nb * 8 + 2 * t;
        const size_t ofs1 = ofs0 + (size_t)8 * HID;
        *(uint32_t*)&g_ah[ofs0] = packh2(o[nb][0] * i0, o[nb][1] * i0);
        *(uint32_t*)&g_ah[ofs1] = packh2(o[nb][2] * i1, o[nb][3] * i1);
    }
}

// ================= global rows: MMA over all 2048 keys =================
#define GA_QSZ   (32 * ATS * 2)
#define GA_TILES (2 * 2 * 2 * ATILE * 2)
#define GA_OBUF  (2 * 16 * 64 * 4)
#define GA_SMEM  (GA_QSZ + GA_TILES + GA_OBUF + 256)

__global__ __launch_bounds__(128) void attn_global_mma() {
    extern __shared__ __half smg2[];
    const uint32_t sb = smem_u32(smg2);
    const int h = blockIdx.x;
    const int tid = threadIdx.x, wid = tid >> 5, lane = tid & 31;
    const int g = lane >> 2, t = lane & 3;
    const int rh = wid & 1, kp = wid >> 1;
    const int brow = ((lane >> 4) << 3) + (lane & 7);
    const int bcol = ((lane >> 3) & 1) * 8;

    const uint32_t sQ = sb;
    const uint32_t tiles0 = sb + GA_QSZ;
    float* obuf = (float*)(smg2 + (32 * ATS + 8 * ATILE));
    float* slm  = obuf + 2 * 16 * 64;
    float* sll  = slm + 32;

    {
        const __half* qp = g_qh + (size_t)h * SEQ * 64;
        for (int idx = tid; idx < 256; idx += 128) {
            const int r = idx >> 3, c = idx & 7;
            cp16(sQ + (uint32_t)(r * ATS + c * 8) * 2, qp + (size_t)r * 64 * 64 + c * 8);
        }
    }
    CP_COMMIT();

    auto stage_tiles = [&](int st, int it) {
#pragma unroll
        for (int kpi = 0; kpi < 2; kpi++) {
            const int kt = (it * 2 + kpi) * 64;
            const uint32_t b = tiles0 + (uint32_t)((st * 2 + kpi) * 2) * ATILE * 2;
            const __half* khp = g_kh + (size_t)h * SEQ * 64 + (size_t)kt * 64;
            const __half* vhp = g_vth + (size_t)h * 64 * SEQ + kt;
            for (int idx = tid; idx < 512; idx += 128) {
                const int r = idx >> 3, c = idx & 7;
                const uint32_t so = (uint32_t)(r * ATS + c * 8) * 2;
                cp16(b + so,             khp + r * 64 + c * 8);
                cp16(b + ATILE * 2 + so, vhp + (size_t)r * SEQ + c * 8);
            }
        }
    };

    stage_tiles(0, 0);
    CP_COMMIT();
    CP_WAIT1();
    __syncthreads();

    uint32_t qh[4][4];
    {
        const int ar = rh * 16 + ((lane >> 3) & 1) * 8 + (lane & 7);
        const int ac = (lane >> 4) * 8;
#pragma unroll
        for (int c = 0; c < 4; c++) {
            const uint32_t ad = sQ + (uint32_t)(ar * ATS + c * 16 + ac) * 2;
            ldm_x4(qh[c][0], qh[c][1], qh[c][2], qh[c][3], ad);
        }
    }

    float o[8][4];
#pragma unroll
    for (int nb = 0; nb < 8; nb++)
#pragma unroll
        for (int c = 0; c < 4; c++) o[nb][c] = 0.f;
    float m0 = -1e30f, m1 = -1e30f, l0 = 0.f, l1 = 0.f;

    for (int it = 0; it < 16; it++) {
        if (it + 1 < 16) {
            stage_tiles((it + 1) & 1, it + 1);
            CP_COMMIT();
            CP_WAIT1();
        } else {
            CP_WAIT0();
        }
        __syncthreads();
        const uint32_t b = tiles0 + (uint32_t)(((it & 1) * 2 + kp) * 2) * ATILE * 2;
        attn_compute<64, 2>(b, b + ATILE * 2, 0, 0,
                            t, brow, bcol, qh, o, m0, m1, l0, l1);
        __syncthreads();
    }

    __syncthreads();
    if (kp == 1) {
        float* ob = obuf + rh * 16 * 64;
#pragma unroll
        for (int nb = 0; nb < 8; nb++) {
            ob[g * 64 + nb * 8 + 2 * t]           = o[nb][0];
            ob[g * 64 + nb * 8 + 2 * t + 1]       = o[nb][1];
            ob[(g + 8) * 64 + nb * 8 + 2 * t]     = o[nb][2];
            ob[(g + 8) * 64 + nb * 8 + 2 * t + 1] = o[nb][3];
        }
        if (t == 0) {
            slm[rh * 16 + g] = m0; slm[rh * 16 + g + 8] = m1;
            sll[rh * 16 + g] = l0; sll[rh * 16 + g + 8] = l1;
        }
    }
    __syncthreads();
    if (kp == 0) {
        const float pm0 = slm[rh * 16 + g], pm1 = slm[rh * 16 + g + 8];
        const float pl0 = sll[rh * 16 + g], pl1 = sll[rh * 16 + g + 8];
        const float M0 = fmaxf(m0, pm0), M1 = fmaxf(m1, pm1);
        const float e0 = __expf(m0 - M0), f0 = __expf(pm0 - M0);
        const float e1 = __expf(m1 - M1), f1 = __expf(pm1 - M1);
        const float L0 = l0 * e0 + pl0 * f0;
        const float L1 = l1 * e1 + pl1 * f1;
        const float i0 = 1.f / L0, i1 = 1.f / L1;
        float* ob = obuf + rh * 16 * 64;
        const int qi0 = (rh * 16 + g) * 64;
        const int qi1 = (rh * 16 + g + 8) * 64;
#pragma unroll
        for (int nb = 0; nb < 8; nb++) {
            const int cc = nb * 8 + 2 * t;
            const float r00 = (o[nb][0] * e0 + ob[g * 64 + cc] * f0) * i0;
            const float r01 = (o[nb][1] * e0 + ob[g * 64 + cc + 1] * f0) * i0;
            const float r10 = (o[nb][2] * e1 + ob[(g + 8) * 64 + cc] * f1) * i1;
            const float r11 = (o[nb][3] * e1 + ob[(g + 8) * 64 + cc + 1] * f1) * i1;
            const size_t ofs0 = (size_t)qi0 * HID + h * HD + cc;
            const size_t ofs1 = (size_t)qi1 * HID + h * HD + cc;
            *(uint32_t*)&g_ah[ofs0] = packh2(r00, r01);
            *(uint32_t*)&g_ah[ofs1] = packh2(r10, r11);
        }
    }
}

// ---------------- launch: forked-stream DAG (lazy-init handles) ----------------
static cudaStream_t g_s1 = nullptr, g_s2 = nullptr;
static cudaEvent_t  g_eFork, g_eX, g_eWo, g_ePrep, g_eG;

extern "C" void kernel_launch(void* const* d_in, const int* in_sizes, int n_in,
                              void* d_out, int out_size) {
    const float* x    = (const float*)d_in[0];
    const float* Wqkv = (const float*)d_in[1];
    const float* Wout = (const float*)d_in[2];
    float* out = (float*)d_out;

    float* qkv = nullptr;
    cudaGetSymbolAddress((void**)&qkv, g_qkv);
    __half *xh, *wqh, *woh, *ah;
    cudaGetSymbolAddress((void**)&xh,  g_xh);
    cudaGetSymbolAddress((void**)&wqh, g_wqh);
    cudaGetSymbolAddress((void**)&woh, g_woh);
    cudaGetSymbolAddress((void**)&ah,  g_ah);

    if (g_s1 == nullptr) {
        cudaStreamCreateWithFlags(&g_s1, cudaStreamNonBlocking);
        cudaStreamCreateWithFlags(&g_s2, cudaStreamNonBlocking);
        cudaEventCreateWithFlags(&g_eFork, cudaEventDisableTiming);
        cudaEventCreateWithFlags(&g_eX,    cudaEventDisableTiming);
        cudaEventCreateWithFlags(&g_eWo,   cudaEventDisableTiming);
        cudaEventCreateWithFlags(&g_ePrep, cudaEventDisableTiming);
        cudaEventCreateWithFlags(&g_eG,    cudaEventDisableTiming);
        cudaFuncSetAttribute((const void*)gemm_f16p<64, 64>,
                             cudaFuncAttributeMaxDynamicSharedMemorySize, GFP64_SMEM);
        cudaFuncSetAttribute(attn_mma, cudaFuncAttributeMaxDynamicSharedMemorySize, AT_SMEM);
        cudaFuncSetAttribute(attn_global_mma, cudaFuncAttributeMaxDynamicSharedMemorySize, GA_SMEM);
    }

    // fork s1 off the (capture) default stream
    cudaEventRecord(g_eFork, 0);
    cudaStreamWaitEvent(g_s1, g_eFork, 0);

    // s1: x -> fp16, then Wout -> fp16 (only needed by final GEMM)
    conv_half<<<(SEQ * HID / 4 + 255) / 256, 256, 0, g_s1>>>(x, xh, SEQ * HID / 4);
    cudaEventRecord(g_eX, g_s1);
    conv_half<<<(HID * HID / 4 + 255) / 256, 256, 0, g_s1>>>(Wout, woh, HID * HID / 4);
    cudaEventRecord(g_eWo, g_s1);

    // default: Wqkv -> fp16, then QKV GEMM (plain fp16, 64x128 tiles)
    conv_half<<<(H3 * HID / 4 + 255) / 256, 256>>>(Wqkv, wqh, H3 * HID / 4);
    cudaStreamWaitEvent(0, g_eX, 0);
    gemm_f16p<64, 64><<<dim3(H3 / 128, SEQ / 64), 256, GFP64_SMEM>>>(xh, wqh, qkv, SEQ, H3, HID);

    // default: per-head fp16 operands
    prep_attn<<<dim3(SEQ / 64, NHEAD), 256>>>();
    cudaEventRecord(g_ePrep, 0);

    // s2: global-row attention in parallel with banded attention
    cudaStreamWaitEvent(g_s2, g_ePrep, 0);
    attn_global_mma<<<NHEAD, 128, GA_SMEM, g_s2>>>();
    cudaEventRecord(g_eG, g_s2);

    // default: banded attention
    attn_mma<<<dim3(SEQ / 64, NHEAD), 128, AT_SMEM>>>();

    // join everything, then out-projection (plain fp16)
    cudaStreamWaitEvent(0, g_eG, 0);
    cudaStreamWaitEvent(0, g_eWo, 0);
    gemm_f16p<64, 64><<<dim3(HID / 128, SEQ / 64), 256, GFP64_SMEM>>>(ah, woh, out, SEQ, HID, HID);
}